// round 7
// baseline (speedup 1.0000x reference)
#include <cuda_runtime.h>
#include <math.h>

#define H      24
#define D      128
#define DIM    3072
#define S_TXT  512
#define S_IMG  2048
#define S_TOT  2560
#define EPS    1e-6f

// ---------------- scratch (device globals; no allocations allowed) ----------
__device__ float g_Q[(size_t)H * S_TOT * D];   // [h][t][d], t: 0..511 txt, 512.. img
__device__ float g_K[(size_t)H * S_TOT * D];
__device__ float g_V[(size_t)H * S_TOT * D];
__device__ float g_A[(size_t)S_TOT * DIM];     // joint attn out, [t][h*D+d]

// ---------------------------------------------------------------------------
// SGEMM: C = A(MxDIM) * B(DIMxDIM) + bias, BM=BN=128, BK=8, 256 thr, 8x8/thr
// MODE 0: write head layout  C[(head*S_TOT + row_off + m)*D + (n&127)]
// MODE 1: write row-major    C[m*DIM + n]
// ---------------------------------------------------------------------------
template <int MODE>
__global__ void __launch_bounds__(256, 2)
sgemm_bias(const float* __restrict__ A, const float* __restrict__ B,
           const float* __restrict__ bias, float* __restrict__ C,
           int M, int row_off)
{
    __shared__ float As[2][8][132];   // [buf][k][m] (transposed), padded
    __shared__ float Bs[2][8][128];   // [buf][k][n]

    const int tid = threadIdx.x;
    const int bx = blockIdx.x;        // N tile (== head index for MODE 0)
    const int by = blockIdx.y;        // M tile
    const int m0 = by * 128;
    const int n0 = bx * 128;

    const int arow = tid >> 1;            // 0..127
    const int acol = (tid & 1) << 2;      // 0 or 4
    const int brow = tid >> 5;            // 0..7
    const int bcol = (tid & 31) << 2;     // 0..124

    const float* Aptr = A + (size_t)(m0 + arow) * DIM + acol;
    const float* Bptr = B + (size_t)brow * DIM + n0 + bcol;

    // preload k-tile 0 into buffer 0
    {
        float4 ra = *(const float4*)(Aptr);
        float4 rb = *(const float4*)(Bptr);
        As[0][acol + 0][arow] = ra.x;
        As[0][acol + 1][arow] = ra.y;
        As[0][acol + 2][arow] = ra.z;
        As[0][acol + 3][arow] = ra.w;
        *(float4*)&Bs[0][brow][bcol] = rb;
    }
    __syncthreads();

    float acc[8][8];
    #pragma unroll
    for (int i = 0; i < 8; ++i)
        #pragma unroll
        for (int j = 0; j < 8; ++j) acc[i][j] = 0.f;

    const int ty = tid >> 4;   // 0..15
    const int tx = tid & 15;   // 0..15

    const int NKT = DIM / 8;   // 384
    for (int kt = 0; kt < NKT; ++kt) {
        const int cb = kt & 1;
        const bool pre = (kt + 1 < NKT);
        float4 na, nb;
        if (pre) {
            na = *(const float4*)(Aptr + (kt + 1) * 8);
            nb = *(const float4*)(Bptr + (size_t)(kt + 1) * 8 * DIM);
        }
        #pragma unroll
        for (int kk = 0; kk < 8; ++kk) {
            float4 a0 = *(const float4*)&As[cb][kk][ty * 8];
            float4 a1 = *(const float4*)&As[cb][kk][ty * 8 + 4];
            float4 b0 = *(const float4*)&Bs[cb][kk][tx * 8];
            float4 b1 = *(const float4*)&Bs[cb][kk][tx * 8 + 4];
            float av[8] = {a0.x, a0.y, a0.z, a0.w, a1.x, a1.y, a1.z, a1.w};
            float bv[8] = {b0.x, b0.y, b0.z, b0.w, b1.x, b1.y, b1.z, b1.w};
            #pragma unroll
            for (int i = 0; i < 8; ++i)
                #pragma unroll
                for (int j = 0; j < 8; ++j)
                    acc[i][j] += av[i] * bv[j];
        }
        if (pre) {
            const int nbuf = cb ^ 1;
            As[nbuf][acol + 0][arow] = na.x;
            As[nbuf][acol + 1][arow] = na.y;
            As[nbuf][acol + 2][arow] = na.z;
            As[nbuf][acol + 3][arow] = na.w;
            *(float4*)&Bs[nbuf][brow][bcol] = nb;
        }
        __syncthreads();
    }

    // epilogue
    #pragma unroll
    for (int i = 0; i < 8; ++i) {
        const int m = m0 + ty * 8 + i;
        #pragma unroll
        for (int j = 0; j < 8; ++j) {
            const int col = tx * 8 + j;
            const int n = n0 + col;
            const float v = acc[i][j] + bias[n];
            if (MODE == 0)
                C[((size_t)bx * S_TOT + row_off + m) * D + col] = v;
            else
                C[(size_t)m * DIM + n] = v;
        }
    }
}

// ---------------------------------------------------------------------------
// RMSNorm + RoPE, one warp per (head, token) row of 128 floats, in place.
// t < S_TXT -> txt weights/cos/sin; else img (local position t - S_TXT).
// ---------------------------------------------------------------------------
__global__ void __launch_bounds__(256)
norm_rope(float* __restrict__ X,
          const float* __restrict__ w_img, const float* __restrict__ w_txt,
          const float* __restrict__ img_cos, const float* __restrict__ img_sin,
          const float* __restrict__ txt_cos, const float* __restrict__ txt_sin)
{
    const int warp = (blockIdx.x * blockDim.x + threadIdx.x) >> 5;
    const int lane = threadIdx.x & 31;
    if (warp >= H * S_TOT) return;
    const int t = warp % S_TOT;
    const int h = warp / S_TOT;
    float* row = X + ((size_t)h * S_TOT + t) * D;
    const int d0 = lane * 4;

    float4 x = *(const float4*)(row + d0);
    float ss = x.x * x.x + x.y * x.y + x.z * x.z + x.w * x.w;
    #pragma unroll
    for (int o = 16; o > 0; o >>= 1) ss += __shfl_xor_sync(0xffffffffu, ss, o);
    const float inv = rsqrtf(ss * (1.f / 128.f) + EPS);

    const float* w;
    const float* cs;
    const float* sn;
    if (t < S_TXT) { w = w_txt; cs = txt_cos + (size_t)t * D;          sn = txt_sin + (size_t)t * D; }
    else           { w = w_img; cs = img_cos + (size_t)(t - S_TXT) * D; sn = img_sin + (size_t)(t - S_TXT) * D; }

    float4 wv = *(const float4*)(w + d0);
    float4 c  = *(const float4*)(cs + d0);
    float4 s  = *(const float4*)(sn + d0);

    const float y0 = x.x * inv * wv.x;
    const float y1 = x.y * inv * wv.y;
    const float y2 = x.z * inv * wv.z;
    const float y3 = x.w * inv * wv.w;

    float4 o;
    o.x = y0 * c.x - y1 * s.x;
    o.y = y1 * c.y + y0 * s.y;
    o.z = y2 * c.z - y3 * s.z;
    o.w = y3 * c.w + y2 * s.w;
    *(float4*)(row + d0) = o;
}

// ---------------------------------------------------------------------------
// fp32 flash attention.  grid (S_TOT/64, H), 256 threads.
// BM=BN=64, D=128. Online softmax. Output -> joint layout g_A[t][h*D+d].
// ---------------------------------------------------------------------------
#define FA_BM 64
#define FA_BN 64
#define QS_STRIDE 132
#define VS_STRIDE 136
#define SS_STRIDE 68
#define FA_SMEM_FLOATS (FA_BM*QS_STRIDE + FA_BN*QS_STRIDE + FA_BN*VS_STRIDE + FA_BM*SS_STRIDE + 3*FA_BM)
#define FA_SMEM_BYTES  (FA_SMEM_FLOATS * sizeof(float))

__global__ void __launch_bounds__(256, 1)
flash_attn(const float* __restrict__ Q, const float* __restrict__ K,
           const float* __restrict__ V, float* __restrict__ Aout)
{
    extern __shared__ float sm[];
    float* Qs   = sm;
    float* Ks   = Qs + FA_BM * QS_STRIDE;
    float* Vs   = Ks + FA_BN * QS_STRIDE;
    float* Ss   = Vs + FA_BN * VS_STRIDE;
    float* m_s  = Ss + FA_BM * SS_STRIDE;
    float* l_s  = m_s + FA_BM;
    float* al_s = l_s + FA_BM;

    const int tid = threadIdx.x;
    const int h  = blockIdx.y;
    const int m0 = blockIdx.x * FA_BM;

    const float* Qg = Q + ((size_t)h * S_TOT + m0) * D;
    const float* Kg = K + (size_t)h * S_TOT * D;
    const float* Vg = V + (size_t)h * S_TOT * D;

    // load Q tile (64 x 128 floats = 2048 float4)
    #pragma unroll
    for (int i = 0; i < 8; ++i) {
        const int idx = tid + i * 256;
        const int r = idx >> 5;
        const int c = (idx & 31) << 2;
        *(float4*)(Qs + r * QS_STRIDE + c) = *(const float4*)(Qg + r * D + c);
    }
    if (tid < FA_BM) { m_s[tid] = -1e30f; l_s[tid] = 0.f; }

    float acc[4][8];
    #pragma unroll
    for (int i = 0; i < 4; ++i)
        #pragma unroll
        for (int j = 0; j < 8; ++j) acc[i][j] = 0.f;

    const int tr = tid >> 4;   // 0..15
    const int tc = tid & 15;   // 0..15
    const float scale = 0.08838834764831845f;   // 1/sqrt(128)

    __syncthreads();

    for (int kt = 0; kt < S_TOT / FA_BN; ++kt) {
        const float* kg = Kg + (size_t)kt * FA_BN * D;
        const float* vg = Vg + (size_t)kt * FA_BN * D;
        #pragma unroll
        for (int i = 0; i < 8; ++i) {
            const int idx = tid + i * 256;
            const int r = idx >> 5;
            const int c = (idx & 31) << 2;
            *(float4*)(Ks + r * QS_STRIDE + c) = *(const float4*)(kg + r * D + c);
            *(float4*)(Vs + r * VS_STRIDE + c) = *(const float4*)(vg + r * D + c);
        }
        __syncthreads();

        // S = Q K^T (each thread 4x4)
        float s_acc[4][4];
        #pragma unroll
        for (int i = 0; i < 4; ++i)
            #pragma unroll
            for (int j = 0; j < 4; ++j) s_acc[i][j] = 0.f;

        #pragma unroll 4
        for (int k = 0; k < D; k += 4) {
            float4 qv[4], kv[4];
            #pragma unroll
            for (int i = 0; i < 4; ++i) qv[i] = *(const float4*)(Qs + (tr * 4 + i) * QS_STRIDE + k);
            #pragma unroll
            for (int j = 0; j < 4; ++j) kv[j] = *(const float4*)(Ks + (tc * 4 + j) * QS_STRIDE + k);
            #pragma unroll
            for (int i = 0; i < 4; ++i)
                #pragma unroll
                for (int j = 0; j < 4; ++j)
                    s_acc[i][j] += qv[i].x * kv[j].x + qv[i].y * kv[j].y +
                                   qv[i].z * kv[j].z + qv[i].w * kv[j].w;
        }
        #pragma unroll
        for (int i = 0; i < 4; ++i)
            #pragma unroll
            for (int j = 0; j < 4; ++j)
                Ss[(tr * 4 + i) * SS_STRIDE + tc * 4 + j] = s_acc[i][j] * scale;
        __syncthreads();

        // online softmax (one thread per row)
        if (tid < FA_BM) {
            const int r = tid;
            float* srow = Ss + r * SS_STRIDE;
            const float mold = m_s[r];
            float mx = mold;
            #pragma unroll 8
            for (int n = 0; n < FA_BN; ++n) mx = fmaxf(mx, srow[n]);
            const float al = __expf(mold - mx);
            float sum = 0.f;
            #pragma unroll 8
            for (int n = 0; n < FA_BN; ++n) {
                const float p = __expf(srow[n] - mx);
                srow[n] = p;
                sum += p;
            }
            m_s[r] = mx;
            l_s[r] = l_s[r] * al + sum;
            al_s[r] = al;
        }
        __syncthreads();

        // rescale accumulators, then O += P * V  (each thread 4 rows x 8 cols)
        float alr[4];
        #pragma unroll
        for (int i = 0; i < 4; ++i) alr[i] = al_s[tr * 4 + i];
        #pragma unroll
        for (int i = 0; i < 4; ++i)
            #pragma unroll
            for (int j = 0; j < 8; ++j) acc[i][j] *= alr[i];

        #pragma unroll 4
        for (int n = 0; n < FA_BN; ++n) {
            float pp[4];
            #pragma unroll
            for (int i = 0; i < 4; ++i) pp[i] = Ss[(tr * 4 + i) * SS_STRIDE + n];
            float4 v0 = *(const float4*)(Vs + n * VS_STRIDE + tc * 8);
            float4 v1 = *(const float4*)(Vs + n * VS_STRIDE + tc * 8 + 4);
            float vv[8] = {v0.x, v0.y, v0.z, v0.w, v1.x, v1.y, v1.z, v1.w};
            #pragma unroll
            for (int i = 0; i < 4; ++i)
                #pragma unroll
                for (int j = 0; j < 8; ++j)
                    acc[i][j] += pp[i] * vv[j];
        }
        __syncthreads();
    }

    // epilogue: normalize by l, write joint layout
    #pragma unroll
    for (int i = 0; i < 4; ++i) {
        const int r = tr * 4 + i;
        const float inv = 1.f / l_s[r];
        const int t = m0 + r;
        float* outp = Aout + (size_t)t * DIM + h * D + tc * 8;
        float4 o0 = make_float4(acc[i][0] * inv, acc[i][1] * inv, acc[i][2] * inv, acc[i][3] * inv);
        float4 o1 = make_float4(acc[i][4] * inv, acc[i][5] * inv, acc[i][6] * inv, acc[i][7] * inv);
        *(float4*)(outp)     = o0;
        *(float4*)(outp + 4) = o1;
    }
}

// ---------------------------------------------------------------------------
extern "C" void kernel_launch(void* const* d_in, const int* in_sizes, int n_in,
                              void* d_out, int out_size)
{
    const float* hid     = (const float*)d_in[0];
    const float* enc     = (const float*)d_in[1];
    const float* img_cos = (const float*)d_in[2];
    const float* img_sin = (const float*)d_in[3];
    const float* txt_cos = (const float*)d_in[4];
    const float* txt_sin = (const float*)d_in[5];
    const float* wq  = (const float*)d_in[6];
    const float* bq  = (const float*)d_in[7];
    const float* wk  = (const float*)d_in[8];
    const float* bk  = (const float*)d_in[9];
    const float* wv  = (const float*)d_in[10];
    const float* bv  = (const float*)d_in[11];
    const float* awq = (const float*)d_in[12];
    const float* abq = (const float*)d_in[13];
    const float* awk = (const float*)d_in[14];
    const float* abk = (const float*)d_in[15];
    const float* awv = (const float*)d_in[16];
    const float* abv = (const float*)d_in[17];
    const float* wo  = (const float*)d_in[18];
    const float* bo  = (const float*)d_in[19];
    const float* awo = (const float*)d_in[20];
    const float* abo = (const float*)d_in[21];
    const float* nq  = (const float*)d_in[22];
    const float* nk  = (const float*)d_in[23];
    const float* anq = (const float*)d_in[24];
    const float* ank = (const float*)d_in[25];
    float* out = (float*)d_out;

    float *Qp, *Kp, *Vp, *Ap;
    cudaGetSymbolAddress((void**)&Qp, g_Q);
    cudaGetSymbolAddress((void**)&Kp, g_K);
    cudaGetSymbolAddress((void**)&Vp, g_V);
    cudaGetSymbolAddress((void**)&Ap, g_A);

    const dim3 gImg(DIM / 128, S_IMG / 128);
    const dim3 gTxt(DIM / 128, S_TXT / 128);

    // QKV projections into head layout (txt tokens at rows 0..511, img at 512..)
    sgemm_bias<0><<<gImg, 256>>>(hid, wq, bq, Qp, S_IMG, S_TXT);
    sgemm_bias<0><<<gImg, 256>>>(hid, wk, bk, Kp, S_IMG, S_TXT);
    sgemm_bias<0><<<gImg, 256>>>(hid, wv, bv, Vp, S_IMG, S_TXT);
    sgemm_bias<0><<<gTxt, 256>>>(enc, awq, abq, Qp, S_TXT, 0);
    sgemm_bias<0><<<gTxt, 256>>>(enc, awk, abk, Kp, S_TXT, 0);
    sgemm_bias<0><<<gTxt, 256>>>(enc, awv, abv, Vp, S_TXT, 0);

    // rmsnorm + rope on Q and K (V untouched)
    const int nr_blocks = (H * S_TOT) / 8;   // 8 warps per block
    norm_rope<<<nr_blocks, 256>>>(Qp, nq, anq, img_cos, img_sin, txt_cos, txt_sin);
    norm_rope<<<nr_blocks, 256>>>(Kp, nk, ank, img_cos, img_sin, txt_cos, txt_sin);

    // joint flash attention
    cudaFuncSetAttribute(flash_attn, cudaFuncAttributeMaxDynamicSharedMemorySize,
                         (int)FA_SMEM_BYTES);
    flash_attn<<<dim3(S_TOT / FA_BM, H), 256, FA_SMEM_BYTES>>>(Qp, Kp, Vp, Ap);

    // output projections: img rows of joint are 512.., txt rows 0..511
    sgemm_bias<1><<<gImg, 256>>>(Ap + (size_t)S_TXT * DIM, wo, bo, out, S_IMG, 0);
    sgemm_bias<1><<<gTxt, 256>>>(Ap, awo, abo, out + (size_t)S_IMG * DIM, S_TXT, 0);
}

// round 8
// speedup vs baseline: 1.0031x; 1.0031x over previous
#include <cuda_runtime.h>
#include <math.h>

#define H      24
#define D      128
#define DIM    3072
#define S_TXT  512
#define S_IMG  2048
#define S_TOT  2560
#define EPS    1e-6f

// ---------------- scratch (device globals; no allocations allowed) ----------
__device__ float g_Q[(size_t)H * S_TOT * D];   // [h][t][d], t: 0..511 txt, 512.. img
__device__ float g_K[(size_t)H * S_TOT * D];
__device__ float g_V[(size_t)H * S_TOT * D];
__device__ float g_A[(size_t)S_TOT * DIM];     // joint attn out, [t][h*D+d]

// ---------------------------------------------------------------------------
// SGEMM: C = A(MxDIM) * B(DIMxDIM) + bias, BM=BN=128, BK=8, 256 thr, 8x8/thr
// MODE 0: write head layout  C[(head*S_TOT + row_off + m)*D + (n&127)]
// MODE 1: write row-major    C[m*DIM + n]
// ---------------------------------------------------------------------------
template <int MODE>
__global__ void __launch_bounds__(256, 2)
sgemm_bias(const float* __restrict__ A, const float* __restrict__ B,
           const float* __restrict__ bias, float* __restrict__ C,
           int M, int row_off)
{
    __shared__ float As[2][8][132];   // [buf][k][m] (transposed), padded
    __shared__ float Bs[2][8][128];   // [buf][k][n]

    const int tid = threadIdx.x;
    const int bx = blockIdx.x;        // N tile (== head index for MODE 0)
    const int by = blockIdx.y;        // M tile
    const int m0 = by * 128;
    const int n0 = bx * 128;

    const int arow = tid >> 1;            // 0..127
    const int acol = (tid & 1) << 2;      // 0 or 4
    const int brow = tid >> 5;            // 0..7
    const int bcol = (tid & 31) << 2;     // 0..124

    const float* Aptr = A + (size_t)(m0 + arow) * DIM + acol;
    const float* Bptr = B + (size_t)brow * DIM + n0 + bcol;

    // preload k-tile 0 into buffer 0
    {
        float4 ra = *(const float4*)(Aptr);
        float4 rb = *(const float4*)(Bptr);
        As[0][acol + 0][arow] = ra.x;
        As[0][acol + 1][arow] = ra.y;
        As[0][acol + 2][arow] = ra.z;
        As[0][acol + 3][arow] = ra.w;
        *(float4*)&Bs[0][brow][bcol] = rb;
    }
    __syncthreads();

    float acc[8][8];
    #pragma unroll
    for (int i = 0; i < 8; ++i)
        #pragma unroll
        for (int j = 0; j < 8; ++j) acc[i][j] = 0.f;

    const int ty = tid >> 4;   // 0..15
    const int tx = tid & 15;   // 0..15

    const int NKT = DIM / 8;   // 384
    for (int kt = 0; kt < NKT; ++kt) {
        const int cb = kt & 1;
        const bool pre = (kt + 1 < NKT);
        float4 na, nb;
        if (pre) {
            na = *(const float4*)(Aptr + (kt + 1) * 8);
            nb = *(const float4*)(Bptr + (size_t)(kt + 1) * 8 * DIM);
        }
        #pragma unroll
        for (int kk = 0; kk < 8; ++kk) {
            float4 a0 = *(const float4*)&As[cb][kk][ty * 8];
            float4 a1 = *(const float4*)&As[cb][kk][ty * 8 + 4];
            float4 b0 = *(const float4*)&Bs[cb][kk][tx * 8];
            float4 b1 = *(const float4*)&Bs[cb][kk][tx * 8 + 4];
            float av[8] = {a0.x, a0.y, a0.z, a0.w, a1.x, a1.y, a1.z, a1.w};
            float bv[8] = {b0.x, b0.y, b0.z, b0.w, b1.x, b1.y, b1.z, b1.w};
            #pragma unroll
            for (int i = 0; i < 8; ++i)
                #pragma unroll
                for (int j = 0; j < 8; ++j)
                    acc[i][j] += av[i] * bv[j];
        }
        if (pre) {
            const int nbuf = cb ^ 1;
            As[nbuf][acol + 0][arow] = na.x;
            As[nbuf][acol + 1][arow] = na.y;
            As[nbuf][acol + 2][arow] = na.z;
            As[nbuf][acol + 3][arow] = na.w;
            *(float4*)&Bs[nbuf][brow][bcol] = nb;
        }
        __syncthreads();
    }

    // epilogue
    #pragma unroll
    for (int i = 0; i < 8; ++i) {
        const int m = m0 + ty * 8 + i;
        #pragma unroll
        for (int j = 0; j < 8; ++j) {
            const int col = tx * 8 + j;
            const int n = n0 + col;
            const float v = acc[i][j] + bias[n];
            if (MODE == 0)
                C[((size_t)bx * S_TOT + row_off + m) * D + col] = v;
            else
                C[(size_t)m * DIM + n] = v;
        }
    }
}

// ---------------------------------------------------------------------------
// RMSNorm + RoPE, one warp per (head, token) row of 128 floats, in place.
// t < S_TXT -> txt weights/cos/sin; else img (local position t - S_TXT).
// ---------------------------------------------------------------------------
__global__ void __launch_bounds__(256)
norm_rope(float* __restrict__ X,
          const float* __restrict__ w_img, const float* __restrict__ w_txt,
          const float* __restrict__ img_cos, const float* __restrict__ img_sin,
          const float* __restrict__ txt_cos, const float* __restrict__ txt_sin)
{
    const int warp = (blockIdx.x * blockDim.x + threadIdx.x) >> 5;
    const int lane = threadIdx.x & 31;
    if (warp >= H * S_TOT) return;
    const int t = warp % S_TOT;
    const int h = warp / S_TOT;
    float* row = X + ((size_t)h * S_TOT + t) * D;
    const int d0 = lane * 4;

    float4 x = *(const float4*)(row + d0);
    float ss = x.x * x.x + x.y * x.y + x.z * x.z + x.w * x.w;
    #pragma unroll
    for (int o = 16; o > 0; o >>= 1) ss += __shfl_xor_sync(0xffffffffu, ss, o);
    const float inv = rsqrtf(ss * (1.f / 128.f) + EPS);

    const float* w;
    const float* cs;
    const float* sn;
    if (t < S_TXT) { w = w_txt; cs = txt_cos + (size_t)t * D;          sn = txt_sin + (size_t)t * D; }
    else           { w = w_img; cs = img_cos + (size_t)(t - S_TXT) * D; sn = img_sin + (size_t)(t - S_TXT) * D; }

    float4 wv = *(const float4*)(w + d0);
    float4 c  = *(const float4*)(cs + d0);
    float4 s  = *(const float4*)(sn + d0);

    const float y0 = x.x * inv * wv.x;
    const float y1 = x.y * inv * wv.y;
    const float y2 = x.z * inv * wv.z;
    const float y3 = x.w * inv * wv.w;

    float4 o;
    o.x = y0 * c.x - y1 * s.x;
    o.y = y1 * c.y + y0 * s.y;
    o.z = y2 * c.z - y3 * s.z;
    o.w = y3 * c.w + y2 * s.w;
    *(float4*)(row + d0) = o;
}

// ---------------------------------------------------------------------------
// fp32 flash attention.  grid (S_TOT/64, H), 256 threads.
// BM=BN=64, D=128. Online softmax. Output -> joint layout g_A[t][h*D+d].
// ---------------------------------------------------------------------------
#define FA_BM 64
#define FA_BN 64
#define QS_STRIDE 132
#define VS_STRIDE 136
#define SS_STRIDE 68
#define FA_SMEM_FLOATS (FA_BM*QS_STRIDE + FA_BN*QS_STRIDE + FA_BN*VS_STRIDE + FA_BM*SS_STRIDE + 3*FA_BM)
#define FA_SMEM_BYTES  (FA_SMEM_FLOATS * sizeof(float))

__global__ void __launch_bounds__(256, 1)
flash_attn(const float* __restrict__ Q, const float* __restrict__ K,
           const float* __restrict__ V, float* __restrict__ Aout)
{
    extern __shared__ float sm[];
    float* Qs   = sm;
    float* Ks   = Qs + FA_BM * QS_STRIDE;
    float* Vs   = Ks + FA_BN * QS_STRIDE;
    float* Ss   = Vs + FA_BN * VS_STRIDE;
    float* m_s  = Ss + FA_BM * SS_STRIDE;
    float* l_s  = m_s + FA_BM;
    float* al_s = l_s + FA_BM;

    const int tid = threadIdx.x;
    const int h  = blockIdx.y;
    const int m0 = blockIdx.x * FA_BM;

    const float* Qg = Q + ((size_t)h * S_TOT + m0) * D;
    const float* Kg = K + (size_t)h * S_TOT * D;
    const float* Vg = V + (size_t)h * S_TOT * D;

    // load Q tile (64 x 128 floats = 2048 float4)
    #pragma unroll
    for (int i = 0; i < 8; ++i) {
        const int idx = tid + i * 256;
        const int r = idx >> 5;
        const int c = (idx & 31) << 2;
        *(float4*)(Qs + r * QS_STRIDE + c) = *(const float4*)(Qg + r * D + c);
    }
    if (tid < FA_BM) { m_s[tid] = -1e30f; l_s[tid] = 0.f; }

    float acc[4][8];
    #pragma unroll
    for (int i = 0; i < 4; ++i)
        #pragma unroll
        for (int j = 0; j < 8; ++j) acc[i][j] = 0.f;

    const int tr = tid >> 4;   // 0..15
    const int tc = tid & 15;   // 0..15
    const float scale = 0.08838834764831845f;   // 1/sqrt(128)

    __syncthreads();

    for (int kt = 0; kt < S_TOT / FA_BN; ++kt) {
        const float* kg = Kg + (size_t)kt * FA_BN * D;
        const float* vg = Vg + (size_t)kt * FA_BN * D;
        #pragma unroll
        for (int i = 0; i < 8; ++i) {
            const int idx = tid + i * 256;
            const int r = idx >> 5;
            const int c = (idx & 31) << 2;
            *(float4*)(Ks + r * QS_STRIDE + c) = *(const float4*)(kg + r * D + c);
            *(float4*)(Vs + r * VS_STRIDE + c) = *(const float4*)(vg + r * D + c);
        }
        __syncthreads();

        // S = Q K^T (each thread 4x4)
        float s_acc[4][4];
        #pragma unroll
        for (int i = 0; i < 4; ++i)
            #pragma unroll
            for (int j = 0; j < 4; ++j) s_acc[i][j] = 0.f;

        #pragma unroll 4
        for (int k = 0; k < D; k += 4) {
            float4 qv[4], kv[4];
            #pragma unroll
            for (int i = 0; i < 4; ++i) qv[i] = *(const float4*)(Qs + (tr * 4 + i) * QS_STRIDE + k);
            #pragma unroll
            for (int j = 0; j < 4; ++j) kv[j] = *(const float4*)(Ks + (tc * 4 + j) * QS_STRIDE + k);
            #pragma unroll
            for (int i = 0; i < 4; ++i)
                #pragma unroll
                for (int j = 0; j < 4; ++j)
                    s_acc[i][j] += qv[i].x * kv[j].x + qv[i].y * kv[j].y +
                                   qv[i].z * kv[j].z + qv[i].w * kv[j].w;
        }
        #pragma unroll
        for (int i = 0; i < 4; ++i)
            #pragma unroll
            for (int j = 0; j < 4; ++j)
                Ss[(tr * 4 + i) * SS_STRIDE + tc * 4 + j] = s_acc[i][j] * scale;
        __syncthreads();

        // online softmax (one thread per row)
        if (tid < FA_BM) {
            const int r = tid;
            float* srow = Ss + r * SS_STRIDE;
            const float mold = m_s[r];
            float mx = mold;
            #pragma unroll 8
            for (int n = 0; n < FA_BN; ++n) mx = fmaxf(mx, srow[n]);
            const float al = __expf(mold - mx);
            float sum = 0.f;
            #pragma unroll 8
            for (int n = 0; n < FA_BN; ++n) {
                const float p = __expf(srow[n] - mx);
                srow[n] = p;
                sum += p;
            }
            m_s[r] = mx;
            l_s[r] = l_s[r] * al + sum;
            al_s[r] = al;
        }
        __syncthreads();

        // rescale accumulators, then O += P * V  (each thread 4 rows x 8 cols)
        float alr[4];
        #pragma unroll
        for (int i = 0; i < 4; ++i) alr[i] = al_s[tr * 4 + i];
        #pragma unroll
        for (int i = 0; i < 4; ++i)
            #pragma unroll
            for (int j = 0; j < 8; ++j) acc[i][j] *= alr[i];

        #pragma unroll 4
        for (int n = 0; n < FA_BN; ++n) {
            float pp[4];
            #pragma unroll
            for (int i = 0; i < 4; ++i) pp[i] = Ss[(tr * 4 + i) * SS_STRIDE + n];
            float4 v0 = *(const float4*)(Vs + n * VS_STRIDE + tc * 8);
            float4 v1 = *(const float4*)(Vs + n * VS_STRIDE + tc * 8 + 4);
            float vv[8] = {v0.x, v0.y, v0.z, v0.w, v1.x, v1.y, v1.z, v1.w};
            #pragma unroll
            for (int i = 0; i < 4; ++i)
                #pragma unroll
                for (int j = 0; j < 8; ++j)
                    acc[i][j] += pp[i] * vv[j];
        }
        __syncthreads();
    }

    // epilogue: normalize by l, write joint layout
    #pragma unroll
    for (int i = 0; i < 4; ++i) {
        const int r = tr * 4 + i;
        const float inv = 1.f / l_s[r];
        const int t = m0 + r;
        float* outp = Aout + (size_t)t * DIM + h * D + tc * 8;
        float4 o0 = make_float4(acc[i][0] * inv, acc[i][1] * inv, acc[i][2] * inv, acc[i][3] * inv);
        float4 o1 = make_float4(acc[i][4] * inv, acc[i][5] * inv, acc[i][6] * inv, acc[i][7] * inv);
        *(float4*)(outp)     = o0;
        *(float4*)(outp + 4) = o1;
    }
}

// ---------------------------------------------------------------------------
extern "C" void kernel_launch(void* const* d_in, const int* in_sizes, int n_in,
                              void* d_out, int out_size)
{
    const float* hid     = (const float*)d_in[0];
    const float* enc     = (const float*)d_in[1];
    const float* img_cos = (const float*)d_in[2];
    const float* img_sin = (const float*)d_in[3];
    const float* txt_cos = (const float*)d_in[4];
    const float* txt_sin = (const float*)d_in[5];
    const float* wq  = (const float*)d_in[6];
    const float* bq  = (const float*)d_in[7];
    const float* wk  = (const float*)d_in[8];
    const float* bk  = (const float*)d_in[9];
    const float* wv  = (const float*)d_in[10];
    const float* bv  = (const float*)d_in[11];
    const float* awq = (const float*)d_in[12];
    const float* abq = (const float*)d_in[13];
    const float* awk = (const float*)d_in[14];
    const float* abk = (const float*)d_in[15];
    const float* awv = (const float*)d_in[16];
    const float* abv = (const float*)d_in[17];
    const float* wo  = (const float*)d_in[18];
    const float* bo  = (const float*)d_in[19];
    const float* awo = (const float*)d_in[20];
    const float* abo = (const float*)d_in[21];
    const float* nq  = (const float*)d_in[22];
    const float* nk  = (const float*)d_in[23];
    const float* anq = (const float*)d_in[24];
    const float* ank = (const float*)d_in[25];
    float* out = (float*)d_out;

    float *Qp, *Kp, *Vp, *Ap;
    cudaGetSymbolAddress((void**)&Qp, g_Q);
    cudaGetSymbolAddress((void**)&Kp, g_K);
    cudaGetSymbolAddress((void**)&Vp, g_V);
    cudaGetSymbolAddress((void**)&Ap, g_A);

    const dim3 gImg(DIM / 128, S_IMG / 128);
    const dim3 gTxt(DIM / 128, S_TXT / 128);

    // QKV projections into head layout (txt tokens at rows 0..511, img at 512..)
    sgemm_bias<0><<<gImg, 256>>>(hid, wq, bq, Qp, S_IMG, S_TXT);
    sgemm_bias<0><<<gImg, 256>>>(hid, wk, bk, Kp, S_IMG, S_TXT);
    sgemm_bias<0><<<gImg, 256>>>(hid, wv, bv, Vp, S_IMG, S_TXT);
    sgemm_bias<0><<<gTxt, 256>>>(enc, awq, abq, Qp, S_TXT, 0);
    sgemm_bias<0><<<gTxt, 256>>>(enc, awk, abk, Kp, S_TXT, 0);
    sgemm_bias<0><<<gTxt, 256>>>(enc, awv, abv, Vp, S_TXT, 0);

    // rmsnorm + rope on Q and K (V untouched)
    const int nr_blocks = (H * S_TOT) / 8;   // 8 warps per block
    norm_rope<<<nr_blocks, 256>>>(Qp, nq, anq, img_cos, img_sin, txt_cos, txt_sin);
    norm_rope<<<nr_blocks, 256>>>(Kp, nk, ank, img_cos, img_sin, txt_cos, txt_sin);

    // joint flash attention
    cudaFuncSetAttribute(flash_attn, cudaFuncAttributeMaxDynamicSharedMemorySize,
                         (int)FA_SMEM_BYTES);
    flash_attn<<<dim3(S_TOT / FA_BM, H), 256, FA_SMEM_BYTES>>>(Qp, Kp, Vp, Ap);

    // output projections: img rows of joint are 512.., txt rows 0..511
    sgemm_bias<1><<<gImg, 256>>>(Ap + (size_t)S_TXT * DIM, wo, bo, out, S_IMG, 0);
    sgemm_bias<1><<<gTxt, 256>>>(Ap, awo, abo, out + (size_t)S_IMG * DIM, S_TXT, 0);
}

// round 9
// speedup vs baseline: 1.0031x; 1.0000x over previous
#include <cuda_runtime.h>
#include <math.h>

#define H      24
#define D      128
#define DIM    3072
#define S_TXT  512
#define S_IMG  2048
#define S_TOT  2560
#define EPS    1e-6f

// ---------------- scratch (device globals; no allocations allowed) ----------
__device__ float g_Q[(size_t)H * S_TOT * D];   // [h][t][d], t: 0..511 txt, 512.. img
__device__ float g_K[(size_t)H * S_TOT * D];
__device__ float g_V[(size_t)H * S_TOT * D];
__device__ float g_A[(size_t)S_TOT * DIM];     // joint attn out, [t][h*D+d]

// ---------------------------------------------------------------------------
// SGEMM: C = A(MxDIM) * B(DIMxDIM) + bias, BM=BN=128, BK=8, 256 thr, 8x8/thr
// MODE 0: write head layout  C[(head*S_TOT + row_off + m)*D + (n&127)]
// MODE 1: write row-major    C[m*DIM + n]
// ---------------------------------------------------------------------------
template <int MODE>
__global__ void __launch_bounds__(256, 2)
sgemm_bias(const float* __restrict__ A, const float* __restrict__ B,
           const float* __restrict__ bias, float* __restrict__ C,
           int M, int row_off)
{
    __shared__ float As[2][8][132];   // [buf][k][m] (transposed), padded
    __shared__ float Bs[2][8][128];   // [buf][k][n]

    const int tid = threadIdx.x;
    const int bx = blockIdx.x;        // N tile (== head index for MODE 0)
    const int by = blockIdx.y;        // M tile
    const int m0 = by * 128;
    const int n0 = bx * 128;

    const int arow = tid >> 1;            // 0..127
    const int acol = (tid & 1) << 2;      // 0 or 4
    const int brow = tid >> 5;            // 0..7
    const int bcol = (tid & 31) << 2;     // 0..124

    const float* Aptr = A + (size_t)(m0 + arow) * DIM + acol;
    const float* Bptr = B + (size_t)brow * DIM + n0 + bcol;

    // preload k-tile 0 into buffer 0
    {
        float4 ra = *(const float4*)(Aptr);
        float4 rb = *(const float4*)(Bptr);
        As[0][acol + 0][arow] = ra.x;
        As[0][acol + 1][arow] = ra.y;
        As[0][acol + 2][arow] = ra.z;
        As[0][acol + 3][arow] = ra.w;
        *(float4*)&Bs[0][brow][bcol] = rb;
    }
    __syncthreads();

    float acc[8][8];
    #pragma unroll
    for (int i = 0; i < 8; ++i)
        #pragma unroll
        for (int j = 0; j < 8; ++j) acc[i][j] = 0.f;

    const int ty = tid >> 4;   // 0..15
    const int tx = tid & 15;   // 0..15

    const int NKT = DIM / 8;   // 384
    for (int kt = 0; kt < NKT; ++kt) {
        const int cb = kt & 1;
        const bool pre = (kt + 1 < NKT);
        float4 na, nb;
        if (pre) {
            na = *(const float4*)(Aptr + (kt + 1) * 8);
            nb = *(const float4*)(Bptr + (size_t)(kt + 1) * 8 * DIM);
        }
        #pragma unroll
        for (int kk = 0; kk < 8; ++kk) {
            float4 a0 = *(const float4*)&As[cb][kk][ty * 8];
            float4 a1 = *(const float4*)&As[cb][kk][ty * 8 + 4];
            float4 b0 = *(const float4*)&Bs[cb][kk][tx * 8];
            float4 b1 = *(const float4*)&Bs[cb][kk][tx * 8 + 4];
            float av[8] = {a0.x, a0.y, a0.z, a0.w, a1.x, a1.y, a1.z, a1.w};
            float bv[8] = {b0.x, b0.y, b0.z, b0.w, b1.x, b1.y, b1.z, b1.w};
            #pragma unroll
            for (int i = 0; i < 8; ++i)
                #pragma unroll
                for (int j = 0; j < 8; ++j)
                    acc[i][j] += av[i] * bv[j];
        }
        if (pre) {
            const int nbuf = cb ^ 1;
            As[nbuf][acol + 0][arow] = na.x;
            As[nbuf][acol + 1][arow] = na.y;
            As[nbuf][acol + 2][arow] = na.z;
            As[nbuf][acol + 3][arow] = na.w;
            *(float4*)&Bs[nbuf][brow][bcol] = nb;
        }
        __syncthreads();
    }

    // epilogue
    #pragma unroll
    for (int i = 0; i < 8; ++i) {
        const int m = m0 + ty * 8 + i;
        #pragma unroll
        for (int j = 0; j < 8; ++j) {
            const int col = tx * 8 + j;
            const int n = n0 + col;
            const float v = acc[i][j] + bias[n];
            if (MODE == 0)
                C[((size_t)bx * S_TOT + row_off + m) * D + col] = v;
            else
                C[(size_t)m * DIM + n] = v;
        }
    }
}

// ---------------------------------------------------------------------------
// RMSNorm + RoPE, one warp per (head, token) row of 128 floats, in place.
// t < S_TXT -> txt weights/cos/sin; else img (local position t - S_TXT).
// ---------------------------------------------------------------------------
__global__ void __launch_bounds__(256)
norm_rope(float* __restrict__ X,
          const float* __restrict__ w_img, const float* __restrict__ w_txt,
          const float* __restrict__ img_cos, const float* __restrict__ img_sin,
          const float* __restrict__ txt_cos, const float* __restrict__ txt_sin)
{
    const int warp = (blockIdx.x * blockDim.x + threadIdx.x) >> 5;
    const int lane = threadIdx.x & 31;
    if (warp >= H * S_TOT) return;
    const int t = warp % S_TOT;
    const int h = warp / S_TOT;
    float* row = X + ((size_t)h * S_TOT + t) * D;
    const int d0 = lane * 4;

    float4 x = *(const float4*)(row + d0);
    float ss = x.x * x.x + x.y * x.y + x.z * x.z + x.w * x.w;
    #pragma unroll
    for (int o = 16; o > 0; o >>= 1) ss += __shfl_xor_sync(0xffffffffu, ss, o);
    const float inv = rsqrtf(ss * (1.f / 128.f) + EPS);

    const float* w;
    const float* cs;
    const float* sn;
    if (t < S_TXT) { w = w_txt; cs = txt_cos + (size_t)t * D;          sn = txt_sin + (size_t)t * D; }
    else           { w = w_img; cs = img_cos + (size_t)(t - S_TXT) * D; sn = img_sin + (size_t)(t - S_TXT) * D; }

    float4 wv = *(const float4*)(w + d0);
    float4 c  = *(const float4*)(cs + d0);
    float4 s  = *(const float4*)(sn + d0);

    const float y0 = x.x * inv * wv.x;
    const float y1 = x.y * inv * wv.y;
    const float y2 = x.z * inv * wv.z;
    const float y3 = x.w * inv * wv.w;

    float4 o;
    o.x = y0 * c.x - y1 * s.x;
    o.y = y1 * c.y + y0 * s.y;
    o.z = y2 * c.z - y3 * s.z;
    o.w = y3 * c.w + y2 * s.w;
    *(float4*)(row + d0) = o;
}

// ---------------------------------------------------------------------------
// fp32 flash attention.  grid (S_TOT/64, H), 256 threads.
// BM=BN=64, D=128. Online softmax. Output -> joint layout g_A[t][h*D+d].
// ---------------------------------------------------------------------------
#define FA_BM 64
#define FA_BN 64
#define QS_STRIDE 132
#define VS_STRIDE 136
#define SS_STRIDE 68
#define FA_SMEM_FLOATS (FA_BM*QS_STRIDE + FA_BN*QS_STRIDE + FA_BN*VS_STRIDE + FA_BM*SS_STRIDE + 3*FA_BM)
#define FA_SMEM_BYTES  (FA_SMEM_FLOATS * sizeof(float))

__global__ void __launch_bounds__(256, 1)
flash_attn(const float* __restrict__ Q, const float* __restrict__ K,
           const float* __restrict__ V, float* __restrict__ Aout)
{
    extern __shared__ float sm[];
    float* Qs   = sm;
    float* Ks   = Qs + FA_BM * QS_STRIDE;
    float* Vs   = Ks + FA_BN * QS_STRIDE;
    float* Ss   = Vs + FA_BN * VS_STRIDE;
    float* m_s  = Ss + FA_BM * SS_STRIDE;
    float* l_s  = m_s + FA_BM;
    float* al_s = l_s + FA_BM;

    const int tid = threadIdx.x;
    const int h  = blockIdx.y;
    const int m0 = blockIdx.x * FA_BM;

    const float* Qg = Q + ((size_t)h * S_TOT + m0) * D;
    const float* Kg = K + (size_t)h * S_TOT * D;
    const float* Vg = V + (size_t)h * S_TOT * D;

    // load Q tile (64 x 128 floats = 2048 float4)
    #pragma unroll
    for (int i = 0; i < 8; ++i) {
        const int idx = tid + i * 256;
        const int r = idx >> 5;
        const int c = (idx & 31) << 2;
        *(float4*)(Qs + r * QS_STRIDE + c) = *(const float4*)(Qg + r * D + c);
    }
    if (tid < FA_BM) { m_s[tid] = -1e30f; l_s[tid] = 0.f; }

    float acc[4][8];
    #pragma unroll
    for (int i = 0; i < 4; ++i)
        #pragma unroll
        for (int j = 0; j < 8; ++j) acc[i][j] = 0.f;

    const int tr = tid >> 4;   // 0..15
    const int tc = tid & 15;   // 0..15
    const float scale = 0.08838834764831845f;   // 1/sqrt(128)

    __syncthreads();

    for (int kt = 0; kt < S_TOT / FA_BN; ++kt) {
        const float* kg = Kg + (size_t)kt * FA_BN * D;
        const float* vg = Vg + (size_t)kt * FA_BN * D;
        #pragma unroll
        for (int i = 0; i < 8; ++i) {
            const int idx = tid + i * 256;
            const int r = idx >> 5;
            const int c = (idx & 31) << 2;
            *(float4*)(Ks + r * QS_STRIDE + c) = *(const float4*)(kg + r * D + c);
            *(float4*)(Vs + r * VS_STRIDE + c) = *(const float4*)(vg + r * D + c);
        }
        __syncthreads();

        // S = Q K^T (each thread 4x4)
        float s_acc[4][4];
        #pragma unroll
        for (int i = 0; i < 4; ++i)
            #pragma unroll
            for (int j = 0; j < 4; ++j) s_acc[i][j] = 0.f;

        #pragma unroll 4
        for (int k = 0; k < D; k += 4) {
            float4 qv[4], kv[4];
            #pragma unroll
            for (int i = 0; i < 4; ++i) qv[i] = *(const float4*)(Qs + (tr * 4 + i) * QS_STRIDE + k);
            #pragma unroll
            for (int j = 0; j < 4; ++j) kv[j] = *(const float4*)(Ks + (tc * 4 + j) * QS_STRIDE + k);
            #pragma unroll
            for (int i = 0; i < 4; ++i)
                #pragma unroll
                for (int j = 0; j < 4; ++j)
                    s_acc[i][j] += qv[i].x * kv[j].x + qv[i].y * kv[j].y +
                                   qv[i].z * kv[j].z + qv[i].w * kv[j].w;
        }
        #pragma unroll
        for (int i = 0; i < 4; ++i)
            #pragma unroll
            for (int j = 0; j < 4; ++j)
                Ss[(tr * 4 + i) * SS_STRIDE + tc * 4 + j] = s_acc[i][j] * scale;
        __syncthreads();

        // online softmax (one thread per row)
        if (tid < FA_BM) {
            const int r = tid;
            float* srow = Ss + r * SS_STRIDE;
            const float mold = m_s[r];
            float mx = mold;
            #pragma unroll 8
            for (int n = 0; n < FA_BN; ++n) mx = fmaxf(mx, srow[n]);
            const float al = __expf(mold - mx);
            float sum = 0.f;
            #pragma unroll 8
            for (int n = 0; n < FA_BN; ++n) {
                const float p = __expf(srow[n] - mx);
                srow[n] = p;
                sum += p;
            }
            m_s[r] = mx;
            l_s[r] = l_s[r] * al + sum;
            al_s[r] = al;
        }
        __syncthreads();

        // rescale accumulators, then O += P * V  (each thread 4 rows x 8 cols)
        float alr[4];
        #pragma unroll
        for (int i = 0; i < 4; ++i) alr[i] = al_s[tr * 4 + i];
        #pragma unroll
        for (int i = 0; i < 4; ++i)
            #pragma unroll
            for (int j = 0; j < 8; ++j) acc[i][j] *= alr[i];

        #pragma unroll 4
        for (int n = 0; n < FA_BN; ++n) {
            float pp[4];
            #pragma unroll
            for (int i = 0; i < 4; ++i) pp[i] = Ss[(tr * 4 + i) * SS_STRIDE + n];
            float4 v0 = *(const float4*)(Vs + n * VS_STRIDE + tc * 8);
            float4 v1 = *(const float4*)(Vs + n * VS_STRIDE + tc * 8 + 4);
            float vv[8] = {v0.x, v0.y, v0.z, v0.w, v1.x, v1.y, v1.z, v1.w};
            #pragma unroll
            for (int i = 0; i < 4; ++i)
                #pragma unroll
                for (int j = 0; j < 8; ++j)
                    acc[i][j] += pp[i] * vv[j];
        }
        __syncthreads();
    }

    // epilogue: normalize by l, write joint layout
    #pragma unroll
    for (int i = 0; i < 4; ++i) {
        const int r = tr * 4 + i;
        const float inv = 1.f / l_s[r];
        const int t = m0 + r;
        float* outp = Aout + (size_t)t * DIM + h * D + tc * 8;
        float4 o0 = make_float4(acc[i][0] * inv, acc[i][1] * inv, acc[i][2] * inv, acc[i][3] * inv);
        float4 o1 = make_float4(acc[i][4] * inv, acc[i][5] * inv, acc[i][6] * inv, acc[i][7] * inv);
        *(float4*)(outp)     = o0;
        *(float4*)(outp + 4) = o1;
    }
}

// ---------------------------------------------------------------------------
extern "C" void kernel_launch(void* const* d_in, const int* in_sizes, int n_in,
                              void* d_out, int out_size)
{
    const float* hid     = (const float*)d_in[0];
    const float* enc     = (const float*)d_in[1];
    const float* img_cos = (const float*)d_in[2];
    const float* img_sin = (const float*)d_in[3];
    const float* txt_cos = (const float*)d_in[4];
    const float* txt_sin = (const float*)d_in[5];
    const float* wq  = (const float*)d_in[6];
    const float* bq  = (const float*)d_in[7];
    const float* wk  = (const float*)d_in[8];
    const float* bk  = (const float*)d_in[9];
    const float* wv  = (const float*)d_in[10];
    const float* bv  = (const float*)d_in[11];
    const float* awq = (const float*)d_in[12];
    const float* abq = (const float*)d_in[13];
    const float* awk = (const float*)d_in[14];
    const float* abk = (const float*)d_in[15];
    const float* awv = (const float*)d_in[16];
    const float* abv = (const float*)d_in[17];
    const float* wo  = (const float*)d_in[18];
    const float* bo  = (const float*)d_in[19];
    const float* awo = (const float*)d_in[20];
    const float* abo = (const float*)d_in[21];
    const float* nq  = (const float*)d_in[22];
    const float* nk  = (const float*)d_in[23];
    const float* anq = (const float*)d_in[24];
    const float* ank = (const float*)d_in[25];
    float* out = (float*)d_out;

    float *Qp, *Kp, *Vp, *Ap;
    cudaGetSymbolAddress((void**)&Qp, g_Q);
    cudaGetSymbolAddress((void**)&Kp, g_K);
    cudaGetSymbolAddress((void**)&Vp, g_V);
    cudaGetSymbolAddress((void**)&Ap, g_A);

    const dim3 gImg(DIM / 128, S_IMG / 128);
    const dim3 gTxt(DIM / 128, S_TXT / 128);

    // QKV projections into head layout (txt tokens at rows 0..511, img at 512..)
    sgemm_bias<0><<<gImg, 256>>>(hid, wq, bq, Qp, S_IMG, S_TXT);
    sgemm_bias<0><<<gImg, 256>>>(hid, wk, bk, Kp, S_IMG, S_TXT);
    sgemm_bias<0><<<gImg, 256>>>(hid, wv, bv, Vp, S_IMG, S_TXT);
    sgemm_bias<0><<<gTxt, 256>>>(enc, awq, abq, Qp, S_TXT, 0);
    sgemm_bias<0><<<gTxt, 256>>>(enc, awk, abk, Kp, S_TXT, 0);
    sgemm_bias<0><<<gTxt, 256>>>(enc, awv, abv, Vp, S_TXT, 0);

    // rmsnorm + rope on Q and K (V untouched)
    const int nr_blocks = (H * S_TOT) / 8;   // 8 warps per block
    norm_rope<<<nr_blocks, 256>>>(Qp, nq, anq, img_cos, img_sin, txt_cos, txt_sin);
    norm_rope<<<nr_blocks, 256>>>(Kp, nk, ank, img_cos, img_sin, txt_cos, txt_sin);

    // joint flash attention
    cudaFuncSetAttribute(flash_attn, cudaFuncAttributeMaxDynamicSharedMemorySize,
                         (int)FA_SMEM_BYTES);
    flash_attn<<<dim3(S_TOT / FA_BM, H), 256, FA_SMEM_BYTES>>>(Qp, Kp, Vp, Ap);

    // output projections: img rows of joint are 512.., txt rows 0..511
    sgemm_bias<1><<<gImg, 256>>>(Ap + (size_t)S_TXT * DIM, wo, bo, out, S_IMG, 0);
    sgemm_bias<1><<<gTxt, 256>>>(Ap, awo, abo, out + (size_t)S_IMG * DIM, S_TXT, 0);
}

// round 10
// speedup vs baseline: 1.5727x; 1.5678x over previous
#include <cuda_runtime.h>
#include <math.h>
#include <stdint.h>

#define H      24
#define D      128
#define DIM    3072
#define S_TXT  512
#define S_IMG  2048
#define S_TOT  2560
#define EPS    1e-6f

// ---------------- scratch (device globals; no allocations allowed) ----------
__device__ float g_Q[(size_t)H * S_TOT * D];   // [h][t][d]
__device__ float g_K[(size_t)H * S_TOT * D];
__device__ float g_V[(size_t)H * S_TOT * D];
__device__ float g_A[(size_t)S_TOT * DIM];     // joint attn out, [t][h*D+d]

// ---------------- helpers ---------------------------------------------------
__device__ __forceinline__ float tf32r(float x) {
    unsigned u;
    asm("cvt.rna.tf32.f32 %0, %1;" : "=r"(u) : "f"(x));
    return __uint_as_float(u);
}
__device__ __forceinline__ void cp16(uint32_t s, const void* g) {
    asm volatile("cp.async.cg.shared.global [%0], [%1], 16;" :: "r"(s), "l"(g));
}
__device__ __forceinline__ void cp_commit() { asm volatile("cp.async.commit_group;"); }
template <int N>
__device__ __forceinline__ void cp_wait() { asm volatile("cp.async.wait_group %0;" :: "n"(N)); }

// mma.m16n8k8 tf32: A 4 regs (a0:(g,t) a1:(g+8,t) a2:(g,t+4) a3:(g+8,t+4)),
// B 2 regs (b0:(k=t,n=g) b1:(k=t+4,n=g)), C 4 (c0:(g,2t) c1:(g,2t+1) c2/c3: +8 rows)
__device__ __forceinline__ void mma_tf32(float* c, const float* a, float b0, float b1) {
    asm volatile("mma.sync.aligned.m16n8k8.row.col.f32.tf32.tf32.f32 "
                 "{%0,%1,%2,%3}, {%4,%5,%6,%7}, {%8,%9}, {%0,%1,%2,%3};"
        : "+f"(c[0]), "+f"(c[1]), "+f"(c[2]), "+f"(c[3])
        : "r"(__float_as_uint(a[0])), "r"(__float_as_uint(a[1])),
          "r"(__float_as_uint(a[2])), "r"(__float_as_uint(a[3])),
          "r"(__float_as_uint(b0)), "r"(__float_as_uint(b1)));
}

// ---------------------------------------------------------------------------
// SGEMM (unchanged from known-good fp32 version, plus optional tf32 rounding)
// MODE 0: head layout;  MODE 1: row-major.  TF32OUT: round output (for V).
// ---------------------------------------------------------------------------
template <int MODE, int TF32OUT>
__global__ void __launch_bounds__(256, 2)
sgemm_bias(const float* __restrict__ A, const float* __restrict__ B,
           const float* __restrict__ bias, float* __restrict__ C,
           int M, int row_off)
{
    __shared__ float As[2][8][132];
    __shared__ float Bs[2][8][128];

    const int tid = threadIdx.x;
    const int bx = blockIdx.x;
    const int by = blockIdx.y;
    const int m0 = by * 128;
    const int n0 = bx * 128;

    const int arow = tid >> 1;
    const int acol = (tid & 1) << 2;
    const int brow = tid >> 5;
    const int bcol = (tid & 31) << 2;

    const float* Aptr = A + (size_t)(m0 + arow) * DIM + acol;
    const float* Bptr = B + (size_t)brow * DIM + n0 + bcol;

    {
        float4 ra = *(const float4*)(Aptr);
        float4 rb = *(const float4*)(Bptr);
        As[0][acol + 0][arow] = ra.x;
        As[0][acol + 1][arow] = ra.y;
        As[0][acol + 2][arow] = ra.z;
        As[0][acol + 3][arow] = ra.w;
        *(float4*)&Bs[0][brow][bcol] = rb;
    }
    __syncthreads();

    float acc[8][8];
    #pragma unroll
    for (int i = 0; i < 8; ++i)
        #pragma unroll
        for (int j = 0; j < 8; ++j) acc[i][j] = 0.f;

    const int ty = tid >> 4;
    const int tx = tid & 15;

    const int NKT = DIM / 8;
    for (int kt = 0; kt < NKT; ++kt) {
        const int cb = kt & 1;
        const bool pre = (kt + 1 < NKT);
        float4 na, nb;
        if (pre) {
            na = *(const float4*)(Aptr + (kt + 1) * 8);
            nb = *(const float4*)(Bptr + (size_t)(kt + 1) * 8 * DIM);
        }
        #pragma unroll
        for (int kk = 0; kk < 8; ++kk) {
            float4 a0 = *(const float4*)&As[cb][kk][ty * 8];
            float4 a1 = *(const float4*)&As[cb][kk][ty * 8 + 4];
            float4 b0 = *(const float4*)&Bs[cb][kk][tx * 8];
            float4 b1 = *(const float4*)&Bs[cb][kk][tx * 8 + 4];
            float av[8] = {a0.x, a0.y, a0.z, a0.w, a1.x, a1.y, a1.z, a1.w};
            float bv[8] = {b0.x, b0.y, b0.z, b0.w, b1.x, b1.y, b1.z, b1.w};
            #pragma unroll
            for (int i = 0; i < 8; ++i)
                #pragma unroll
                for (int j = 0; j < 8; ++j)
                    acc[i][j] += av[i] * bv[j];
        }
        if (pre) {
            const int nbuf = cb ^ 1;
            As[nbuf][acol + 0][arow] = na.x;
            As[nbuf][acol + 1][arow] = na.y;
            As[nbuf][acol + 2][arow] = na.z;
            As[nbuf][acol + 3][arow] = na.w;
            *(float4*)&Bs[nbuf][brow][bcol] = nb;
        }
        __syncthreads();
    }

    #pragma unroll
    for (int i = 0; i < 8; ++i) {
        const int m = m0 + ty * 8 + i;
        #pragma unroll
        for (int j = 0; j < 8; ++j) {
            const int col = tx * 8 + j;
            const int n = n0 + col;
            float v = acc[i][j] + bias[n];
            if (TF32OUT) v = tf32r(v);
            if (MODE == 0)
                C[((size_t)bx * S_TOT + row_off + m) * D + col] = v;
            else
                C[(size_t)m * DIM + n] = v;
        }
    }
}

// ---------------------------------------------------------------------------
// RMSNorm + RoPE + fold scale + tf32 rounding. One warp per (head, token).
// ---------------------------------------------------------------------------
__global__ void __launch_bounds__(256)
norm_rope(float* __restrict__ X,
          const float* __restrict__ w_img, const float* __restrict__ w_txt,
          const float* __restrict__ img_cos, const float* __restrict__ img_sin,
          const float* __restrict__ txt_cos, const float* __restrict__ txt_sin,
          float scale)
{
    const int warp = (blockIdx.x * blockDim.x + threadIdx.x) >> 5;
    const int lane = threadIdx.x & 31;
    if (warp >= H * S_TOT) return;
    const int t = warp % S_TOT;
    const int h = warp / S_TOT;
    float* row = X + ((size_t)h * S_TOT + t) * D;
    const int d0 = lane * 4;

    float4 x = *(const float4*)(row + d0);
    float ss = x.x * x.x + x.y * x.y + x.z * x.z + x.w * x.w;
    #pragma unroll
    for (int o = 16; o > 0; o >>= 1) ss += __shfl_xor_sync(0xffffffffu, ss, o);
    const float inv = rsqrtf(ss * (1.f / 128.f) + EPS);

    const float* w; const float* cs; const float* sn;
    if (t < S_TXT) { w = w_txt; cs = txt_cos + (size_t)t * D;           sn = txt_sin + (size_t)t * D; }
    else           { w = w_img; cs = img_cos + (size_t)(t - S_TXT) * D; sn = img_sin + (size_t)(t - S_TXT) * D; }

    float4 wv = *(const float4*)(w + d0);
    float4 c  = *(const float4*)(cs + d0);
    float4 s  = *(const float4*)(sn + d0);

    const float y0 = x.x * inv * wv.x;
    const float y1 = x.y * inv * wv.y;
    const float y2 = x.z * inv * wv.z;
    const float y3 = x.w * inv * wv.w;

    float4 o;
    o.x = tf32r((y0 * c.x - y1 * s.x) * scale);
    o.y = tf32r((y1 * c.y + y0 * s.y) * scale);
    o.z = tf32r((y2 * c.z - y3 * s.z) * scale);
    o.w = tf32r((y3 * c.w + y2 * s.w) * scale);
    *(float4*)(row + d0) = o;
}

// ---------------------------------------------------------------------------
// tf32 tensor-core flash attention. grid (S_TOT/128, H), 256 threads (8 warps).
// BM=128, BN=64, D=128. Q frags in regs; K/V double-buffered via cp.async.
// ---------------------------------------------------------------------------
#define KSTR 132
#define VSTR 136
#define PSTR 68
#define FL_NT (S_TOT / 64)
#define FL_SMEM_FLOATS (2*64*KSTR + 2*64*VSTR + 128*PSTR)
#define FL_SMEM_BYTES  (FL_SMEM_FLOATS * sizeof(float))

__global__ void __launch_bounds__(256)
flash_tf32(const float* __restrict__ Q, const float* __restrict__ K,
           const float* __restrict__ V, float* __restrict__ Aout)
{
    extern __shared__ float fsm[];
    float* Ks = fsm;                    // [2][64][KSTR]
    float* Vs = Ks + 2 * 64 * KSTR;     // [2][64][VSTR]
    float* Ps = Vs + 2 * 64 * VSTR;     // [128][PSTR]

    const int tid  = threadIdx.x;
    const int warp = tid >> 5, lane = tid & 31;
    const int g = lane >> 2, t = lane & 3;
    const int h  = blockIdx.y;
    const int m0 = blockIdx.x * 128;
    const int wr = warp * 16;

    const uint32_t sK = (uint32_t)__cvta_generic_to_shared(Ks);
    const uint32_t sV = (uint32_t)__cvta_generic_to_shared(Vs);

    const float* Qg = Q + ((size_t)h * S_TOT + m0 + wr) * D;
    const float* Kg = K + (size_t)h * S_TOT * D;
    const float* Vg = V + (size_t)h * S_TOT * D;

    // Q fragments in registers (already scaled + tf32-rounded by norm_rope)
    float q[16][4];
    #pragma unroll
    for (int kb = 0; kb < 16; ++kb) {
        q[kb][0] = Qg[(size_t)g * D + kb * 8 + t];
        q[kb][1] = Qg[(size_t)(g + 8) * D + kb * 8 + t];
        q[kb][2] = Qg[(size_t)g * D + kb * 8 + t + 4];
        q[kb][3] = Qg[(size_t)(g + 8) * D + kb * 8 + t + 4];
    }

    float ofr[16][4];
    #pragma unroll
    for (int i = 0; i < 16; ++i)
        #pragma unroll
        for (int j = 0; j < 4; ++j) ofr[i][j] = 0.f;

    float m0r = -1e30f, m1r = -1e30f, l0 = 0.f, l1 = 0.f;

    auto prefetch = [&](int kt, int st) {
        const float* kg = Kg + (size_t)kt * 64 * D;
        const float* vg = Vg + (size_t)kt * 64 * D;
        #pragma unroll
        for (int i = 0; i < 8; ++i) {
            const int idx = tid + i * 256;
            const int r = idx >> 5, c = (idx & 31) << 2;
            cp16(sK + (uint32_t)(st * 64 * KSTR + r * KSTR + c) * 4, kg + (size_t)r * D + c);
            cp16(sV + (uint32_t)(st * 64 * VSTR + r * VSTR + c) * 4, vg + (size_t)r * D + c);
        }
    };

    prefetch(0, 0);
    cp_commit();

    for (int kt = 0; kt < FL_NT; ++kt) {
        const int st = kt & 1;
        if (kt + 1 < FL_NT) { prefetch(kt + 1, st ^ 1); cp_commit(); cp_wait<1>(); }
        else                { cp_wait<0>(); }
        __syncthreads();

        const float* Kb = Ks + st * 64 * KSTR;
        const float* Vb = Vs + st * 64 * VSTR;

        // S = Q K^T  (warp: m16 x n64 x k128)
        float sfr[8][4];
        #pragma unroll
        for (int i = 0; i < 8; ++i)
            #pragma unroll
            for (int j = 0; j < 4; ++j) sfr[i][j] = 0.f;

        #pragma unroll
        for (int kb = 0; kb < 16; ++kb) {
            #pragma unroll
            for (int nt = 0; nt < 8; ++nt) {
                const float b0 = Kb[(nt * 8 + g) * KSTR + kb * 8 + t];
                const float b1 = Kb[(nt * 8 + g) * KSTR + kb * 8 + t + 4];
                mma_tf32(sfr[nt], q[kb], b0, b1);
            }
        }

        // online softmax (rows g and g+8; stats shared within quad t=0..3)
        float mx0 = -1e30f, mx1 = -1e30f;
        #pragma unroll
        for (int nt = 0; nt < 8; ++nt) {
            mx0 = fmaxf(mx0, fmaxf(sfr[nt][0], sfr[nt][1]));
            mx1 = fmaxf(mx1, fmaxf(sfr[nt][2], sfr[nt][3]));
        }
        mx0 = fmaxf(mx0, __shfl_xor_sync(0xffffffffu, mx0, 1));
        mx0 = fmaxf(mx0, __shfl_xor_sync(0xffffffffu, mx0, 2));
        mx1 = fmaxf(mx1, __shfl_xor_sync(0xffffffffu, mx1, 1));
        mx1 = fmaxf(mx1, __shfl_xor_sync(0xffffffffu, mx1, 2));

        const float mn0 = fmaxf(m0r, mx0);
        const float mn1 = fmaxf(m1r, mx1);
        const float al0 = __expf(m0r - mn0);
        const float al1 = __expf(m1r - mn1);
        m0r = mn0; m1r = mn1;

        float* prow0 = Ps + (wr + g) * PSTR;
        float* prow1 = Ps + (wr + 8 + g) * PSTR;
        float s0 = 0.f, s1 = 0.f;
        #pragma unroll
        for (int nt = 0; nt < 8; ++nt) {
            const float p00 = tf32r(__expf(sfr[nt][0] - mn0));
            const float p01 = tf32r(__expf(sfr[nt][1] - mn0));
            const float p10 = tf32r(__expf(sfr[nt][2] - mn1));
            const float p11 = tf32r(__expf(sfr[nt][3] - mn1));
            s0 += p00 + p01;
            s1 += p10 + p11;
            *(float2*)(prow0 + nt * 8 + 2 * t) = make_float2(p00, p01);
            *(float2*)(prow1 + nt * 8 + 2 * t) = make_float2(p10, p11);
        }
        l0 = l0 * al0 + s0;
        l1 = l1 * al1 + s1;

        #pragma unroll
        for (int nt = 0; nt < 16; ++nt) {
            ofr[nt][0] *= al0; ofr[nt][1] *= al0;
            ofr[nt][2] *= al1; ofr[nt][3] *= al1;
        }
        __syncwarp();

        // O += P V  (warp: m16 x n128 x k64)
        #pragma unroll
        for (int kb = 0; kb < 8; ++kb) {
            float a[4];
            a[0] = Ps[(wr + g) * PSTR + kb * 8 + t];
            a[1] = Ps[(wr + 8 + g) * PSTR + kb * 8 + t];
            a[2] = Ps[(wr + g) * PSTR + kb * 8 + t + 4];
            a[3] = Ps[(wr + 8 + g) * PSTR + kb * 8 + t + 4];
            #pragma unroll
            for (int nt = 0; nt < 16; ++nt) {
                const float b0 = Vb[(kb * 8 + t) * VSTR + nt * 8 + g];
                const float b1 = Vb[(kb * 8 + t + 4) * VSTR + nt * 8 + g];
                mma_tf32(ofr[nt], a, b0, b1);
            }
        }
        __syncthreads();
    }

    // finalize: quad-reduce l, normalize, write joint layout
    l0 += __shfl_xor_sync(0xffffffffu, l0, 1);
    l0 += __shfl_xor_sync(0xffffffffu, l0, 2);
    l1 += __shfl_xor_sync(0xffffffffu, l1, 1);
    l1 += __shfl_xor_sync(0xffffffffu, l1, 2);
    const float i0 = 1.f / l0;
    const float i1 = 1.f / l1;

    const int tok0 = m0 + wr + g;
    const int tok1 = tok0 + 8;
    #pragma unroll
    for (int nt = 0; nt < 16; ++nt) {
        *(float2*)(Aout + (size_t)tok0 * DIM + h * D + nt * 8 + 2 * t) =
            make_float2(ofr[nt][0] * i0, ofr[nt][1] * i0);
        *(float2*)(Aout + (size_t)tok1 * DIM + h * D + nt * 8 + 2 * t) =
            make_float2(ofr[nt][2] * i1, ofr[nt][3] * i1);
    }
}

// ---------------------------------------------------------------------------
extern "C" void kernel_launch(void* const* d_in, const int* in_sizes, int n_in,
                              void* d_out, int out_size)
{
    const float* hid     = (const float*)d_in[0];
    const float* enc     = (const float*)d_in[1];
    const float* img_cos = (const float*)d_in[2];
    const float* img_sin = (const float*)d_in[3];
    const float* txt_cos = (const float*)d_in[4];
    const float* txt_sin = (const float*)d_in[5];
    const float* wq  = (const float*)d_in[6];
    const float* bq  = (const float*)d_in[7];
    const float* wk  = (const float*)d_in[8];
    const float* bk  = (const float*)d_in[9];
    const float* wv  = (const float*)d_in[10];
    const float* bv  = (const float*)d_in[11];
    const float* awq = (const float*)d_in[12];
    const float* abq = (const float*)d_in[13];
    const float* awk = (const float*)d_in[14];
    const float* abk = (const float*)d_in[15];
    const float* awv = (const float*)d_in[16];
    const float* abv = (const float*)d_in[17];
    const float* wo  = (const float*)d_in[18];
    const float* bo  = (const float*)d_in[19];
    const float* awo = (const float*)d_in[20];
    const float* abo = (const float*)d_in[21];
    const float* nq  = (const float*)d_in[22];
    const float* nk  = (const float*)d_in[23];
    const float* anq = (const float*)d_in[24];
    const float* ank = (const float*)d_in[25];
    float* out = (float*)d_out;

    float *Qp, *Kp, *Vp, *Ap;
    cudaGetSymbolAddress((void**)&Qp, g_Q);
    cudaGetSymbolAddress((void**)&Kp, g_K);
    cudaGetSymbolAddress((void**)&Vp, g_V);
    cudaGetSymbolAddress((void**)&Ap, g_A);

    const dim3 gImg(DIM / 128, S_IMG / 128);
    const dim3 gTxt(DIM / 128, S_TXT / 128);

    // QKV projections (txt tokens rows 0..511, img 512..). V gets tf32 rounding.
    sgemm_bias<0, 0><<<gImg, 256>>>(hid, wq, bq, Qp, S_IMG, S_TXT);
    sgemm_bias<0, 0><<<gImg, 256>>>(hid, wk, bk, Kp, S_IMG, S_TXT);
    sgemm_bias<0, 1><<<gImg, 256>>>(hid, wv, bv, Vp, S_IMG, S_TXT);
    sgemm_bias<0, 0><<<gTxt, 256>>>(enc, awq, abq, Qp, S_TXT, 0);
    sgemm_bias<0, 0><<<gTxt, 256>>>(enc, awk, abk, Kp, S_TXT, 0);
    sgemm_bias<0, 1><<<gTxt, 256>>>(enc, awv, abv, Vp, S_TXT, 0);

    // rmsnorm + rope; fold 1/sqrt(D) into Q; tf32-round Q and K
    const int nr_blocks = (H * S_TOT) / 8;
    norm_rope<<<nr_blocks, 256>>>(Qp, nq, anq, img_cos, img_sin, txt_cos, txt_sin,
                                  0.08838834764831845f);
    norm_rope<<<nr_blocks, 256>>>(Kp, nk, ank, img_cos, img_sin, txt_cos, txt_sin,
                                  1.0f);

    // joint flash attention (tf32 tensor cores)
    cudaFuncSetAttribute(flash_tf32, cudaFuncAttributeMaxDynamicSharedMemorySize,
                         (int)FL_SMEM_BYTES);
    flash_tf32<<<dim3(S_TOT / 128, H), 256, FL_SMEM_BYTES>>>(Qp, Kp, Vp, Ap);

    // output projections
    sgemm_bias<1, 0><<<gImg, 256>>>(Ap + (size_t)S_TXT * DIM, wo, bo, out, S_IMG, 0);
    sgemm_bias<1, 0><<<gTxt, 256>>>(Ap, awo, abo, out + (size_t)S_IMG * DIM, S_TXT, 0);
}

// round 11
// speedup vs baseline: 1.6461x; 1.0467x over previous
#include <cuda_runtime.h>
#include <math.h>
#include <stdint.h>

#define H      24
#define D      128
#define DIM    3072
#define S_TXT  512
#define S_IMG  2048
#define S_TOT  2560
#define EPS    1e-6f

// ---------------- scratch (device globals; no allocations allowed) ----------
__device__ float g_Q[(size_t)H * S_TOT * D];   // [h][t][d]
__device__ float g_K[(size_t)H * S_TOT * D];
__device__ float g_V[(size_t)H * S_TOT * D];
__device__ float g_A[(size_t)S_TOT * DIM];     // joint attn out, [t][h*D+d]

// ---------------- helpers ---------------------------------------------------
__device__ __forceinline__ float tf32r(float x) {
    unsigned u;
    asm("cvt.rna.tf32.f32 %0, %1;" : "=r"(u) : "f"(x));
    return __uint_as_float(u);
}
__device__ __forceinline__ void cp16(uint32_t s, const void* g) {
    asm volatile("cp.async.cg.shared.global [%0], [%1], 16;" :: "r"(s), "l"(g));
}
__device__ __forceinline__ void cp_commit() { asm volatile("cp.async.commit_group;"); }
template <int N>
__device__ __forceinline__ void cp_wait() { asm volatile("cp.async.wait_group %0;" :: "n"(N)); }

// mma.m16n8k8 tf32: A 4 regs (a0:(g,t) a1:(g+8,t) a2:(g,t+4) a3:(g+8,t+4)),
// B 2 regs (b0:(k=t,n=g) b1:(k=t+4,n=g)), C 4 (c0:(g,2t) c1:(g,2t+1) c2/c3: +8 rows)
__device__ __forceinline__ void mma_tf32(float* c, const float* a, float b0, float b1) {
    asm volatile("mma.sync.aligned.m16n8k8.row.col.f32.tf32.tf32.f32 "
                 "{%0,%1,%2,%3}, {%4,%5,%6,%7}, {%8,%9}, {%0,%1,%2,%3};"
        : "+f"(c[0]), "+f"(c[1]), "+f"(c[2]), "+f"(c[3])
        : "r"(__float_as_uint(a[0])), "r"(__float_as_uint(a[1])),
          "r"(__float_as_uint(a[2])), "r"(__float_as_uint(a[3])),
          "r"(__float_as_uint(b0)), "r"(__float_as_uint(b1)));
}

// ---------------------------------------------------------------------------
// SGEMM (unchanged from known-good fp32 version, plus optional tf32 rounding)
// MODE 0: head layout;  MODE 1: row-major.  TF32OUT: round output (for V).
// ---------------------------------------------------------------------------
template <int MODE, int TF32OUT>
__global__ void __launch_bounds__(256, 2)
sgemm_bias(const float* __restrict__ A, const float* __restrict__ B,
           const float* __restrict__ bias, float* __restrict__ C,
           int M, int row_off)
{
    __shared__ float As[2][8][132];
    __shared__ float Bs[2][8][128];

    const int tid = threadIdx.x;
    const int bx = blockIdx.x;
    const int by = blockIdx.y;
    const int m0 = by * 128;
    const int n0 = bx * 128;

    const int arow = tid >> 1;
    const int acol = (tid & 1) << 2;
    const int brow = tid >> 5;
    const int bcol = (tid & 31) << 2;

    const float* Aptr = A + (size_t)(m0 + arow) * DIM + acol;
    const float* Bptr = B + (size_t)brow * DIM + n0 + bcol;

    {
        float4 ra = *(const float4*)(Aptr);
        float4 rb = *(const float4*)(Bptr);
        As[0][acol + 0][arow] = ra.x;
        As[0][acol + 1][arow] = ra.y;
        As[0][acol + 2][arow] = ra.z;
        As[0][acol + 3][arow] = ra.w;
        *(float4*)&Bs[0][brow][bcol] = rb;
    }
    __syncthreads();

    float acc[8][8];
    #pragma unroll
    for (int i = 0; i < 8; ++i)
        #pragma unroll
        for (int j = 0; j < 8; ++j) acc[i][j] = 0.f;

    const int ty = tid >> 4;
    const int tx = tid & 15;

    const int NKT = DIM / 8;
    for (int kt = 0; kt < NKT; ++kt) {
        const int cb = kt & 1;
        const bool pre = (kt + 1 < NKT);
        float4 na, nb;
        if (pre) {
            na = *(const float4*)(Aptr + (kt + 1) * 8);
            nb = *(const float4*)(Bptr + (size_t)(kt + 1) * 8 * DIM);
        }
        #pragma unroll
        for (int kk = 0; kk < 8; ++kk) {
            float4 a0 = *(const float4*)&As[cb][kk][ty * 8];
            float4 a1 = *(const float4*)&As[cb][kk][ty * 8 + 4];
            float4 b0 = *(const float4*)&Bs[cb][kk][tx * 8];
            float4 b1 = *(const float4*)&Bs[cb][kk][tx * 8 + 4];
            float av[8] = {a0.x, a0.y, a0.z, a0.w, a1.x, a1.y, a1.z, a1.w};
            float bv[8] = {b0.x, b0.y, b0.z, b0.w, b1.x, b1.y, b1.z, b1.w};
            #pragma unroll
            for (int i = 0; i < 8; ++i)
                #pragma unroll
                for (int j = 0; j < 8; ++j)
                    acc[i][j] += av[i] * bv[j];
        }
        if (pre) {
            const int nbuf = cb ^ 1;
            As[nbuf][acol + 0][arow] = na.x;
            As[nbuf][acol + 1][arow] = na.y;
            As[nbuf][acol + 2][arow] = na.z;
            As[nbuf][acol + 3][arow] = na.w;
            *(float4*)&Bs[nbuf][brow][bcol] = nb;
        }
        __syncthreads();
    }

    #pragma unroll
    for (int i = 0; i < 8; ++i) {
        const int m = m0 + ty * 8 + i;
        #pragma unroll
        for (int j = 0; j < 8; ++j) {
            const int col = tx * 8 + j;
            const int n = n0 + col;
            float v = acc[i][j] + bias[n];
            if (TF32OUT) v = tf32r(v);
            if (MODE == 0)
                C[((size_t)bx * S_TOT + row_off + m) * D + col] = v;
            else
                C[(size_t)m * DIM + n] = v;
        }
    }
}

// ---------------------------------------------------------------------------
// RMSNorm + RoPE + fold scale + tf32 rounding. One warp per (head, token).
// ---------------------------------------------------------------------------
__global__ void __launch_bounds__(256)
norm_rope(float* __restrict__ X,
          const float* __restrict__ w_img, const float* __restrict__ w_txt,
          const float* __restrict__ img_cos, const float* __restrict__ img_sin,
          const float* __restrict__ txt_cos, const float* __restrict__ txt_sin,
          float scale)
{
    const int warp = (blockIdx.x * blockDim.x + threadIdx.x) >> 5;
    const int lane = threadIdx.x & 31;
    if (warp >= H * S_TOT) return;
    const int t = warp % S_TOT;
    const int h = warp / S_TOT;
    float* row = X + ((size_t)h * S_TOT + t) * D;
    const int d0 = lane * 4;

    float4 x = *(const float4*)(row + d0);
    float ss = x.x * x.x + x.y * x.y + x.z * x.z + x.w * x.w;
    #pragma unroll
    for (int o = 16; o > 0; o >>= 1) ss += __shfl_xor_sync(0xffffffffu, ss, o);
    const float inv = rsqrtf(ss * (1.f / 128.f) + EPS);

    const float* w; const float* cs; const float* sn;
    if (t < S_TXT) { w = w_txt; cs = txt_cos + (size_t)t * D;           sn = txt_sin + (size_t)t * D; }
    else           { w = w_img; cs = img_cos + (size_t)(t - S_TXT) * D; sn = img_sin + (size_t)(t - S_TXT) * D; }

    float4 wv = *(const float4*)(w + d0);
    float4 c  = *(const float4*)(cs + d0);
    float4 s  = *(const float4*)(sn + d0);

    const float y0 = x.x * inv * wv.x;
    const float y1 = x.y * inv * wv.y;
    const float y2 = x.z * inv * wv.z;
    const float y3 = x.w * inv * wv.w;

    float4 o;
    o.x = tf32r((y0 * c.x - y1 * s.x) * scale);
    o.y = tf32r((y1 * c.y + y0 * s.y) * scale);
    o.z = tf32r((y2 * c.z - y3 * s.z) * scale);
    o.w = tf32r((y3 * c.w + y2 * s.w) * scale);
    *(float4*)(row + d0) = o;
}

// ---------------------------------------------------------------------------
// tf32 tensor-core flash attention. grid (S_TOT/128, H), 256 threads (8 warps).
// BM=128, BN=64, D=128. Q frags in regs; K/V double-buffered via cp.async.
// ---------------------------------------------------------------------------
#define KSTR 132
#define VSTR 136
#define PSTR 68
#define FL_NT (S_TOT / 64)
#define FL_SMEM_FLOATS (2*64*KSTR + 2*64*VSTR + 128*PSTR)
#define FL_SMEM_BYTES  (FL_SMEM_FLOATS * sizeof(float))

__global__ void __launch_bounds__(256)
flash_tf32(const float* __restrict__ Q, const float* __restrict__ K,
           const float* __restrict__ V, float* __restrict__ Aout)
{
    extern __shared__ float fsm[];
    float* Ks = fsm;                    // [2][64][KSTR]
    float* Vs = Ks + 2 * 64 * KSTR;     // [2][64][VSTR]
    float* Ps = Vs + 2 * 64 * VSTR;     // [128][PSTR]

    const int tid  = threadIdx.x;
    const int warp = tid >> 5, lane = tid & 31;
    const int g = lane >> 2, t = lane & 3;
    const int h  = blockIdx.y;
    const int m0 = blockIdx.x * 128;
    const int wr = warp * 16;

    const uint32_t sK = (uint32_t)__cvta_generic_to_shared(Ks);
    const uint32_t sV = (uint32_t)__cvta_generic_to_shared(Vs);

    const float* Qg = Q + ((size_t)h * S_TOT + m0 + wr) * D;
    const float* Kg = K + (size_t)h * S_TOT * D;
    const float* Vg = V + (size_t)h * S_TOT * D;

    // Q fragments in registers (already scaled + tf32-rounded by norm_rope)
    float q[16][4];
    #pragma unroll
    for (int kb = 0; kb < 16; ++kb) {
        q[kb][0] = Qg[(size_t)g * D + kb * 8 + t];
        q[kb][1] = Qg[(size_t)(g + 8) * D + kb * 8 + t];
        q[kb][2] = Qg[(size_t)g * D + kb * 8 + t + 4];
        q[kb][3] = Qg[(size_t)(g + 8) * D + kb * 8 + t + 4];
    }

    float ofr[16][4];
    #pragma unroll
    for (int i = 0; i < 16; ++i)
        #pragma unroll
        for (int j = 0; j < 4; ++j) ofr[i][j] = 0.f;

    float m0r = -1e30f, m1r = -1e30f, l0 = 0.f, l1 = 0.f;

    auto prefetch = [&](int kt, int st) {
        const float* kg = Kg + (size_t)kt * 64 * D;
        const float* vg = Vg + (size_t)kt * 64 * D;
        #pragma unroll
        for (int i = 0; i < 8; ++i) {
            const int idx = tid + i * 256;
            const int r = idx >> 5, c = (idx & 31) << 2;
            cp16(sK + (uint32_t)(st * 64 * KSTR + r * KSTR + c) * 4, kg + (size_t)r * D + c);
            cp16(sV + (uint32_t)(st * 64 * VSTR + r * VSTR + c) * 4, vg + (size_t)r * D + c);
        }
    };

    prefetch(0, 0);
    cp_commit();

    for (int kt = 0; kt < FL_NT; ++kt) {
        const int st = kt & 1;
        if (kt + 1 < FL_NT) { prefetch(kt + 1, st ^ 1); cp_commit(); cp_wait<1>(); }
        else                { cp_wait<0>(); }
        __syncthreads();

        const float* Kb = Ks + st * 64 * KSTR;
        const float* Vb = Vs + st * 64 * VSTR;

        // S = Q K^T  (warp: m16 x n64 x k128)
        float sfr[8][4];
        #pragma unroll
        for (int i = 0; i < 8; ++i)
            #pragma unroll
            for (int j = 0; j < 4; ++j) sfr[i][j] = 0.f;

        #pragma unroll
        for (int kb = 0; kb < 16; ++kb) {
            #pragma unroll
            for (int nt = 0; nt < 8; ++nt) {
                const float b0 = Kb[(nt * 8 + g) * KSTR + kb * 8 + t];
                const float b1 = Kb[(nt * 8 + g) * KSTR + kb * 8 + t + 4];
                mma_tf32(sfr[nt], q[kb], b0, b1);
            }
        }

        // online softmax (rows g and g+8; stats shared within quad t=0..3)
        float mx0 = -1e30f, mx1 = -1e30f;
        #pragma unroll
        for (int nt = 0; nt < 8; ++nt) {
            mx0 = fmaxf(mx0, fmaxf(sfr[nt][0], sfr[nt][1]));
            mx1 = fmaxf(mx1, fmaxf(sfr[nt][2], sfr[nt][3]));
        }
        mx0 = fmaxf(mx0, __shfl_xor_sync(0xffffffffu, mx0, 1));
        mx0 = fmaxf(mx0, __shfl_xor_sync(0xffffffffu, mx0, 2));
        mx1 = fmaxf(mx1, __shfl_xor_sync(0xffffffffu, mx1, 1));
        mx1 = fmaxf(mx1, __shfl_xor_sync(0xffffffffu, mx1, 2));

        const float mn0 = fmaxf(m0r, mx0);
        const float mn1 = fmaxf(m1r, mx1);
        const float al0 = __expf(m0r - mn0);
        const float al1 = __expf(m1r - mn1);
        m0r = mn0; m1r = mn1;

        float* prow0 = Ps + (wr + g) * PSTR;
        float* prow1 = Ps + (wr + 8 + g) * PSTR;
        float s0 = 0.f, s1 = 0.f;
        #pragma unroll
        for (int nt = 0; nt < 8; ++nt) {
            const float p00 = tf32r(__expf(sfr[nt][0] - mn0));
            const float p01 = tf32r(__expf(sfr[nt][1] - mn0));
            const float p10 = tf32r(__expf(sfr[nt][2] - mn1));
            const float p11 = tf32r(__expf(sfr[nt][3] - mn1));
            s0 += p00 + p01;
            s1 += p10 + p11;
            *(float2*)(prow0 + nt * 8 + 2 * t) = make_float2(p00, p01);
            *(float2*)(prow1 + nt * 8 + 2 * t) = make_float2(p10, p11);
        }
        l0 = l0 * al0 + s0;
        l1 = l1 * al1 + s1;

        #pragma unroll
        for (int nt = 0; nt < 16; ++nt) {
            ofr[nt][0] *= al0; ofr[nt][1] *= al0;
            ofr[nt][2] *= al1; ofr[nt][3] *= al1;
        }
        __syncwarp();

        // O += P V  (warp: m16 x n128 x k64)
        #pragma unroll
        for (int kb = 0; kb < 8; ++kb) {
            float a[4];
            a[0] = Ps[(wr + g) * PSTR + kb * 8 + t];
            a[1] = Ps[(wr + 8 + g) * PSTR + kb * 8 + t];
            a[2] = Ps[(wr + g) * PSTR + kb * 8 + t + 4];
            a[3] = Ps[(wr + 8 + g) * PSTR + kb * 8 + t + 4];
            #pragma unroll
            for (int nt = 0; nt < 16; ++nt) {
                const float b0 = Vb[(kb * 8 + t) * VSTR + nt * 8 + g];
                const float b1 = Vb[(kb * 8 + t + 4) * VSTR + nt * 8 + g];
                mma_tf32(ofr[nt], a, b0, b1);
            }
        }
        __syncthreads();
    }

    // finalize: quad-reduce l, normalize, write joint layout
    l0 += __shfl_xor_sync(0xffffffffu, l0, 1);
    l0 += __shfl_xor_sync(0xffffffffu, l0, 2);
    l1 += __shfl_xor_sync(0xffffffffu, l1, 1);
    l1 += __shfl_xor_sync(0xffffffffu, l1, 2);
    const float i0 = 1.f / l0;
    const float i1 = 1.f / l1;

    const int tok0 = m0 + wr + g;
    const int tok1 = tok0 + 8;
    #pragma unroll
    for (int nt = 0; nt < 16; ++nt) {
        *(float2*)(Aout + (size_t)tok0 * DIM + h * D + nt * 8 + 2 * t) =
            make_float2(ofr[nt][0] * i0, ofr[nt][1] * i0);
        *(float2*)(Aout + (size_t)tok1 * DIM + h * D + nt * 8 + 2 * t) =
            make_float2(ofr[nt][2] * i1, ofr[nt][3] * i1);
    }
}

// ---------------------------------------------------------------------------
extern "C" void kernel_launch(void* const* d_in, const int* in_sizes, int n_in,
                              void* d_out, int out_size)
{
    const float* hid     = (const float*)d_in[0];
    const float* enc     = (const float*)d_in[1];
    const float* img_cos = (const float*)d_in[2];
    const float* img_sin = (const float*)d_in[3];
    const float* txt_cos = (const float*)d_in[4];
    const float* txt_sin = (const float*)d_in[5];
    const float* wq  = (const float*)d_in[6];
    const float* bq  = (const float*)d_in[7];
    const float* wk  = (const float*)d_in[8];
    const float* bk  = (const float*)d_in[9];
    const float* wv  = (const float*)d_in[10];
    const float* bv  = (const float*)d_in[11];
    const float* awq = (const float*)d_in[12];
    const float* abq = (const float*)d_in[13];
    const float* awk = (const float*)d_in[14];
    const float* abk = (const float*)d_in[15];
    const float* awv = (const float*)d_in[16];
    const float* abv = (const float*)d_in[17];
    const float* wo  = (const float*)d_in[18];
    const float* bo  = (const float*)d_in[19];
    const float* awo = (const float*)d_in[20];
    const float* abo = (const float*)d_in[21];
    const float* nq  = (const float*)d_in[22];
    const float* nk  = (const float*)d_in[23];
    const float* anq = (const float*)d_in[24];
    const float* ank = (const float*)d_in[25];
    float* out = (float*)d_out;

    float *Qp, *Kp, *Vp, *Ap;
    cudaGetSymbolAddress((void**)&Qp, g_Q);
    cudaGetSymbolAddress((void**)&Kp, g_K);
    cudaGetSymbolAddress((void**)&Vp, g_V);
    cudaGetSymbolAddress((void**)&Ap, g_A);

    const dim3 gImg(DIM / 128, S_IMG / 128);
    const dim3 gTxt(DIM / 128, S_TXT / 128);

    // QKV projections (txt tokens rows 0..511, img 512..). V gets tf32 rounding.
    sgemm_bias<0, 0><<<gImg, 256>>>(hid, wq, bq, Qp, S_IMG, S_TXT);
    sgemm_bias<0, 0><<<gImg, 256>>>(hid, wk, bk, Kp, S_IMG, S_TXT);
    sgemm_bias<0, 1><<<gImg, 256>>>(hid, wv, bv, Vp, S_IMG, S_TXT);
    sgemm_bias<0, 0><<<gTxt, 256>>>(enc, awq, abq, Qp, S_TXT, 0);
    sgemm_bias<0, 0><<<gTxt, 256>>>(enc, awk, abk, Kp, S_TXT, 0);
    sgemm_bias<0, 1><<<gTxt, 256>>>(enc, awv, abv, Vp, S_TXT, 0);

    // rmsnorm + rope; fold 1/sqrt(D) into Q; tf32-round Q and K
    const int nr_blocks = (H * S_TOT) / 8;
    norm_rope<<<nr_blocks, 256>>>(Qp, nq, anq, img_cos, img_sin, txt_cos, txt_sin,
                                  0.08838834764831845f);
    norm_rope<<<nr_blocks, 256>>>(Kp, nk, ank, img_cos, img_sin, txt_cos, txt_sin,
                                  1.0f);

    // joint flash attention (tf32 tensor cores)
    cudaFuncSetAttribute(flash_tf32, cudaFuncAttributeMaxDynamicSharedMemorySize,
                         (int)FL_SMEM_BYTES);
    flash_tf32<<<dim3(S_TOT / 128, H), 256, FL_SMEM_BYTES>>>(Qp, Kp, Vp, Ap);

    // output projections
    sgemm_bias<1, 0><<<gImg, 256>>>(Ap + (size_t)S_TXT * DIM, wo, bo, out, S_IMG, 0);
    sgemm_bias<1, 0><<<gTxt, 256>>>(Ap, awo, abo, out + (size_t)S_IMG * DIM, S_TXT, 0);
}

// round 12
// speedup vs baseline: 4.2372x; 2.5740x over previous
#include <cuda_runtime.h>
#include <math.h>
#include <stdint.h>

#define H      24
#define D      128
#define DIM    3072
#define S_TXT  512
#define S_IMG  2048
#define S_TOT  2560
#define EPS    1e-6f

// ---------------- scratch (device globals; no allocations allowed) ----------
__device__ float g_Q[(size_t)H * S_TOT * D];   // [h][t][d]
__device__ float g_K[(size_t)H * S_TOT * D];
__device__ float g_V[(size_t)H * S_TOT * D];
__device__ float g_A[(size_t)S_TOT * DIM];     // joint attn out, [t][h*D+d]

// ---------------- helpers ---------------------------------------------------
__device__ __forceinline__ float tf32r(float x) {
    unsigned u;
    asm("cvt.rna.tf32.f32 %0, %1;" : "=r"(u) : "f"(x));
    return __uint_as_float(u);
}
__device__ __forceinline__ void cp16(uint32_t s, const void* g) {
    asm volatile("cp.async.cg.shared.global [%0], [%1], 16;" :: "r"(s), "l"(g));
}
__device__ __forceinline__ void cp_commit() { asm volatile("cp.async.commit_group;"); }
template <int N>
__device__ __forceinline__ void cp_wait() { asm volatile("cp.async.wait_group %0;" :: "n"(N)); }

// mma.m16n8k8 tf32: A 4 regs (a0:(g,t) a1:(g+8,t) a2:(g,t+4) a3:(g+8,t+4)),
// B 2 regs (b0:(k=t,n=g) b1:(k=t+4,n=g)), C 4 (c0:(g,2t) c1:(g,2t+1) c2/c3: +8 rows)
__device__ __forceinline__ void mma_tf32(float* c, const float* a, float b0, float b1) {
    asm volatile("mma.sync.aligned.m16n8k8.row.col.f32.tf32.tf32.f32 "
                 "{%0,%1,%2,%3}, {%4,%5,%6,%7}, {%8,%9}, {%0,%1,%2,%3};"
        : "+f"(c[0]), "+f"(c[1]), "+f"(c[2]), "+f"(c[3])
        : "r"(__float_as_uint(a[0])), "r"(__float_as_uint(a[1])),
          "r"(__float_as_uint(a[2])), "r"(__float_as_uint(a[3])),
          "r"(__float_as_uint(b0)), "r"(__float_as_uint(b1)));
}

// ---------------------------------------------------------------------------
// tf32 tensor-core GEMM: C[M][3072] = A[M][3072] * B[3072][3072] + bias
// BM=128 BN=128 BK=32, 256 threads (8 warps as 2x4), warp tile 64x32.
// MODE 0: head layout  C[(bx*S_TOT + row_off + m)*D + (n - bx*128)]
// MODE 1: row major    C[m*DIM + n]
// TF32OUT: round output to tf32 (V path, feeds tf32 flash attention)
// ---------------------------------------------------------------------------
#define GBK  32
#define ASTR 36     // 128 rows x (32 + 4 pad): frag bank = 4g + t, conflict-free
#define BSTR 136    // 32 rows x (128 + 8 pad): frag bank = 8t + g, conflict-free
#define GM_SMEM_FLOATS (2*128*ASTR + 2*GBK*BSTR)
#define GM_SMEM_BYTES  (GM_SMEM_FLOATS * sizeof(float))

template <int MODE, int TF32OUT>
__global__ void __launch_bounds__(256, 2)
gemm_tf32(const float* __restrict__ A, const float* __restrict__ B,
          const float* __restrict__ bias, float* __restrict__ C, int row_off)
{
    extern __shared__ float gsm[];
    float* As = gsm;                     // [2][128][ASTR]
    float* Bs = gsm + 2 * 128 * ASTR;    // [2][GBK][BSTR]

    const int tid  = threadIdx.x;
    const int warp = tid >> 5, lane = tid & 31;
    const int g = lane >> 2, t = lane & 3;
    const int m0 = blockIdx.y * 128;
    const int n0 = blockIdx.x * 128;
    const int wm = (warp >> 2) * 64;     // {0, 64}
    const int wn = (warp & 3) * 32;      // {0, 32, 64, 96}

    const uint32_t sA = (uint32_t)__cvta_generic_to_shared(As);
    const uint32_t sB = (uint32_t)__cvta_generic_to_shared(Bs);

    float acc[4][4][4];
    #pragma unroll
    for (int i = 0; i < 4; ++i)
        #pragma unroll
        for (int j = 0; j < 4; ++j)
            #pragma unroll
            for (int r = 0; r < 4; ++r) acc[i][j][r] = 0.f;

    auto prefetch = [&](int kt, int st) {
        const int k0 = kt * GBK;
        #pragma unroll
        for (int i = 0; i < 4; ++i) {
            const int ia = tid + i * 256;                 // 0..1023
            const int ar = ia >> 3, ac = (ia & 7) * 4;    // 128 rows x 32 cols
            cp16(sA + (uint32_t)(st * 128 * ASTR + ar * ASTR + ac) * 4,
                 A + (size_t)(m0 + ar) * DIM + k0 + ac);
            const int br = ia >> 5, bc = (ia & 31) * 4;   // 32 rows x 128 cols
            cp16(sB + (uint32_t)(st * GBK * BSTR + br * BSTR + bc) * 4,
                 B + (size_t)(k0 + br) * DIM + n0 + bc);
        }
    };

    prefetch(0, 0);
    cp_commit();

    const int NT = DIM / GBK;   // 96
    for (int kt = 0; kt < NT; ++kt) {
        const int st = kt & 1;
        cp_wait<0>();
        __syncthreads();
        if (kt + 1 < NT) { prefetch(kt + 1, st ^ 1); cp_commit(); }

        const float* Ab = As + st * 128 * ASTR;
        const float* Bb = Bs + st * GBK * BSTR;

        #pragma unroll
        for (int ks = 0; ks < GBK; ks += 8) {
            float a[4][4];
            #pragma unroll
            for (int mt = 0; mt < 4; ++mt) {
                const int row = wm + mt * 16;
                a[mt][0] = tf32r(Ab[(row + g) * ASTR + ks + t]);
                a[mt][1] = tf32r(Ab[(row + 8 + g) * ASTR + ks + t]);
                a[mt][2] = tf32r(Ab[(row + g) * ASTR + ks + t + 4]);
                a[mt][3] = tf32r(Ab[(row + 8 + g) * ASTR + ks + t + 4]);
            }
            #pragma unroll
            for (int nt = 0; nt < 4; ++nt) {
                const float b0 = tf32r(Bb[(ks + t) * BSTR + wn + nt * 8 + g]);
                const float b1 = tf32r(Bb[(ks + t + 4) * BSTR + wn + nt * 8 + g]);
                #pragma unroll
                for (int mt = 0; mt < 4; ++mt)
                    mma_tf32(acc[mt][nt], a[mt], b0, b1);
            }
        }
    }

    // epilogue
    #pragma unroll
    for (int mt = 0; mt < 4; ++mt) {
        const int r0 = m0 + wm + mt * 16 + g;
        const int r1 = r0 + 8;
        #pragma unroll
        for (int nt = 0; nt < 4; ++nt) {
            const int cidx = wn + nt * 8 + 2 * t;         // 0..127 within tile
            const int n = n0 + cidx;
            float v0 = acc[mt][nt][0] + bias[n];
            float v1 = acc[mt][nt][1] + bias[n + 1];
            float v2 = acc[mt][nt][2] + bias[n];
            float v3 = acc[mt][nt][3] + bias[n + 1];
            if (TF32OUT) { v0 = tf32r(v0); v1 = tf32r(v1); v2 = tf32r(v2); v3 = tf32r(v3); }
            if (MODE == 0) {
                float* p0 = C + ((size_t)blockIdx.x * S_TOT + row_off + r0) * D + cidx;
                float* p1 = C + ((size_t)blockIdx.x * S_TOT + row_off + r1) * D + cidx;
                *(float2*)p0 = make_float2(v0, v1);
                *(float2*)p1 = make_float2(v2, v3);
            } else {
                *(float2*)(C + (size_t)r0 * DIM + n) = make_float2(v0, v1);
                *(float2*)(C + (size_t)r1 * DIM + n) = make_float2(v2, v3);
            }
        }
    }
}

// ---------------------------------------------------------------------------
// RMSNorm + RoPE + fold scale + tf32 rounding. One warp per (head, token).
// ---------------------------------------------------------------------------
__global__ void __launch_bounds__(256)
norm_rope(float* __restrict__ X,
          const float* __restrict__ w_img, const float* __restrict__ w_txt,
          const float* __restrict__ img_cos, const float* __restrict__ img_sin,
          const float* __restrict__ txt_cos, const float* __restrict__ txt_sin,
          float scale)
{
    const int warp = (blockIdx.x * blockDim.x + threadIdx.x) >> 5;
    const int lane = threadIdx.x & 31;
    if (warp >= H * S_TOT) return;
    const int t = warp % S_TOT;
    const int h = warp / S_TOT;
    float* row = X + ((size_t)h * S_TOT + t) * D;
    const int d0 = lane * 4;

    float4 x = *(const float4*)(row + d0);
    float ss = x.x * x.x + x.y * x.y + x.z * x.z + x.w * x.w;
    #pragma unroll
    for (int o = 16; o > 0; o >>= 1) ss += __shfl_xor_sync(0xffffffffu, ss, o);
    const float inv = rsqrtf(ss * (1.f / 128.f) + EPS);

    const float* w; const float* cs; const float* sn;
    if (t < S_TXT) { w = w_txt; cs = txt_cos + (size_t)t * D;           sn = txt_sin + (size_t)t * D; }
    else           { w = w_img; cs = img_cos + (size_t)(t - S_TXT) * D; sn = img_sin + (size_t)(t - S_TXT) * D; }

    float4 wv = *(const float4*)(w + d0);
    float4 c  = *(const float4*)(cs + d0);
    float4 s  = *(const float4*)(sn + d0);

    const float y0 = x.x * inv * wv.x;
    const float y1 = x.y * inv * wv.y;
    const float y2 = x.z * inv * wv.z;
    const float y3 = x.w * inv * wv.w;

    float4 o;
    o.x = tf32r((y0 * c.x - y1 * s.x) * scale);
    o.y = tf32r((y1 * c.y + y0 * s.y) * scale);
    o.z = tf32r((y2 * c.z - y3 * s.z) * scale);
    o.w = tf32r((y3 * c.w + y2 * s.w) * scale);
    *(float4*)(row + d0) = o;
}

// ---------------------------------------------------------------------------
// tf32 tensor-core flash attention (unchanged from R11 — proven fast).
// grid (S_TOT/128, H), 256 threads (8 warps). BM=128, BN=64, D=128.
// ---------------------------------------------------------------------------
#define KSTR 132
#define VSTR 136
#define PSTR 68
#define FL_NT (S_TOT / 64)
#define FL_SMEM_FLOATS (2*64*KSTR + 2*64*VSTR + 128*PSTR)
#define FL_SMEM_BYTES  (FL_SMEM_FLOATS * sizeof(float))

__global__ void __launch_bounds__(256)
flash_tf32(const float* __restrict__ Q, const float* __restrict__ K,
           const float* __restrict__ V, float* __restrict__ Aout)
{
    extern __shared__ float fsm[];
    float* Ks = fsm;                    // [2][64][KSTR]
    float* Vs = Ks + 2 * 64 * KSTR;     // [2][64][VSTR]
    float* Ps = Vs + 2 * 64 * VSTR;     // [128][PSTR]

    const int tid  = threadIdx.x;
    const int warp = tid >> 5, lane = tid & 31;
    const int g = lane >> 2, t = lane & 3;
    const int h  = blockIdx.y;
    const int m0 = blockIdx.x * 128;
    const int wr = warp * 16;

    const uint32_t sK = (uint32_t)__cvta_generic_to_shared(Ks);
    const uint32_t sV = (uint32_t)__cvta_generic_to_shared(Vs);

    const float* Qg = Q + ((size_t)h * S_TOT + m0 + wr) * D;
    const float* Kg = K + (size_t)h * S_TOT * D;
    const float* Vg = V + (size_t)h * S_TOT * D;

    float q[16][4];
    #pragma unroll
    for (int kb = 0; kb < 16; ++kb) {
        q[kb][0] = Qg[(size_t)g * D + kb * 8 + t];
        q[kb][1] = Qg[(size_t)(g + 8) * D + kb * 8 + t];
        q[kb][2] = Qg[(size_t)g * D + kb * 8 + t + 4];
        q[kb][3] = Qg[(size_t)(g + 8) * D + kb * 8 + t + 4];
    }

    float ofr[16][4];
    #pragma unroll
    for (int i = 0; i < 16; ++i)
        #pragma unroll
        for (int j = 0; j < 4; ++j) ofr[i][j] = 0.f;

    float m0r = -1e30f, m1r = -1e30f, l0 = 0.f, l1 = 0.f;

    auto prefetch = [&](int kt, int st) {
        const float* kg = Kg + (size_t)kt * 64 * D;
        const float* vg = Vg + (size_t)kt * 64 * D;
        #pragma unroll
        for (int i = 0; i < 8; ++i) {
            const int idx = tid + i * 256;
            const int r = idx >> 5, c = (idx & 31) << 2;
            cp16(sK + (uint32_t)(st * 64 * KSTR + r * KSTR + c) * 4, kg + (size_t)r * D + c);
            cp16(sV + (uint32_t)(st * 64 * VSTR + r * VSTR + c) * 4, vg + (size_t)r * D + c);
        }
    };

    prefetch(0, 0);
    cp_commit();

    for (int kt = 0; kt < FL_NT; ++kt) {
        const int st = kt & 1;
        if (kt + 1 < FL_NT) { prefetch(kt + 1, st ^ 1); cp_commit(); cp_wait<1>(); }
        else                { cp_wait<0>(); }
        __syncthreads();

        const float* Kb = Ks + st * 64 * KSTR;
        const float* Vb = Vs + st * 64 * VSTR;

        float sfr[8][4];
        #pragma unroll
        for (int i = 0; i < 8; ++i)
            #pragma unroll
            for (int j = 0; j < 4; ++j) sfr[i][j] = 0.f;

        #pragma unroll
        for (int kb = 0; kb < 16; ++kb) {
            #pragma unroll
            for (int nt = 0; nt < 8; ++nt) {
                const float b0 = Kb[(nt * 8 + g) * KSTR + kb * 8 + t];
                const float b1 = Kb[(nt * 8 + g) * KSTR + kb * 8 + t + 4];
                mma_tf32(sfr[nt], q[kb], b0, b1);
            }
        }

        float mx0 = -1e30f, mx1 = -1e30f;
        #pragma unroll
        for (int nt = 0; nt < 8; ++nt) {
            mx0 = fmaxf(mx0, fmaxf(sfr[nt][0], sfr[nt][1]));
            mx1 = fmaxf(mx1, fmaxf(sfr[nt][2], sfr[nt][3]));
        }
        mx0 = fmaxf(mx0, __shfl_xor_sync(0xffffffffu, mx0, 1));
        mx0 = fmaxf(mx0, __shfl_xor_sync(0xffffffffu, mx0, 2));
        mx1 = fmaxf(mx1, __shfl_xor_sync(0xffffffffu, mx1, 1));
        mx1 = fmaxf(mx1, __shfl_xor_sync(0xffffffffu, mx1, 2));

        const float mn0 = fmaxf(m0r, mx0);
        const float mn1 = fmaxf(m1r, mx1);
        const float al0 = __expf(m0r - mn0);
        const float al1 = __expf(m1r - mn1);
        m0r = mn0; m1r = mn1;

        float* prow0 = Ps + (wr + g) * PSTR;
        float* prow1 = Ps + (wr + 8 + g) * PSTR;
        float s0 = 0.f, s1 = 0.f;
        #pragma unroll
        for (int nt = 0; nt < 8; ++nt) {
            const float p00 = tf32r(__expf(sfr[nt][0] - mn0));
            const float p01 = tf32r(__expf(sfr[nt][1] - mn0));
            const float p10 = tf32r(__expf(sfr[nt][2] - mn1));
            const float p11 = tf32r(__expf(sfr[nt][3] - mn1));
            s0 += p00 + p01;
            s1 += p10 + p11;
            *(float2*)(prow0 + nt * 8 + 2 * t) = make_float2(p00, p01);
            *(float2*)(prow1 + nt * 8 + 2 * t) = make_float2(p10, p11);
        }
        l0 = l0 * al0 + s0;
        l1 = l1 * al1 + s1;

        #pragma unroll
        for (int nt = 0; nt < 16; ++nt) {
            ofr[nt][0] *= al0; ofr[nt][1] *= al0;
            ofr[nt][2] *= al1; ofr[nt][3] *= al1;
        }
        __syncwarp();

        #pragma unroll
        for (int kb = 0; kb < 8; ++kb) {
            float a[4];
            a[0] = Ps[(wr + g) * PSTR + kb * 8 + t];
            a[1] = Ps[(wr + 8 + g) * PSTR + kb * 8 + t];
            a[2] = Ps[(wr + g) * PSTR + kb * 8 + t + 4];
            a[3] = Ps[(wr + 8 + g) * PSTR + kb * 8 + t + 4];
            #pragma unroll
            for (int nt = 0; nt < 16; ++nt) {
                const float b0 = Vb[(kb * 8 + t) * VSTR + nt * 8 + g];
                const float b1 = Vb[(kb * 8 + t + 4) * VSTR + nt * 8 + g];
                mma_tf32(ofr[nt], a, b0, b1);
            }
        }
        __syncthreads();
    }

    l0 += __shfl_xor_sync(0xffffffffu, l0, 1);
    l0 += __shfl_xor_sync(0xffffffffu, l0, 2);
    l1 += __shfl_xor_sync(0xffffffffu, l1, 1);
    l1 += __shfl_xor_sync(0xffffffffu, l1, 2);
    const float i0 = 1.f / l0;
    const float i1 = 1.f / l1;

    const int tok0 = m0 + wr + g;
    const int tok1 = tok0 + 8;
    #pragma unroll
    for (int nt = 0; nt < 16; ++nt) {
        *(float2*)(Aout + (size_t)tok0 * DIM + h * D + nt * 8 + 2 * t) =
            make_float2(ofr[nt][0] * i0, ofr[nt][1] * i0);
        *(float2*)(Aout + (size_t)tok1 * DIM + h * D + nt * 8 + 2 * t) =
            make_float2(ofr[nt][2] * i1, ofr[nt][3] * i1);
    }
}

// ---------------------------------------------------------------------------
extern "C" void kernel_launch(void* const* d_in, const int* in_sizes, int n_in,
                              void* d_out, int out_size)
{
    const float* hid     = (const float*)d_in[0];
    const float* enc     = (const float*)d_in[1];
    const float* img_cos = (const float*)d_in[2];
    const float* img_sin = (const float*)d_in[3];
    const float* txt_cos = (const float*)d_in[4];
    const float* txt_sin = (const float*)d_in[5];
    const float* wq  = (const float*)d_in[6];
    const float* bq  = (const float*)d_in[7];
    const float* wk  = (const float*)d_in[8];
    const float* bk  = (const float*)d_in[9];
    const float* wv  = (const float*)d_in[10];
    const float* bv  = (const float*)d_in[11];
    const float* awq = (const float*)d_in[12];
    const float* abq = (const float*)d_in[13];
    const float* awk = (const float*)d_in[14];
    const float* abk = (const float*)d_in[15];
    const float* awv = (const float*)d_in[16];
    const float* abv = (const float*)d_in[17];
    const float* wo  = (const float*)d_in[18];
    const float* bo  = (const float*)d_in[19];
    const float* awo = (const float*)d_in[20];
    const float* abo = (const float*)d_in[21];
    const float* nq  = (const float*)d_in[22];
    const float* nk  = (const float*)d_in[23];
    const float* anq = (const float*)d_in[24];
    const float* ank = (const float*)d_in[25];
    float* out = (float*)d_out;

    float *Qp, *Kp, *Vp, *Ap;
    cudaGetSymbolAddress((void**)&Qp, g_Q);
    cudaGetSymbolAddress((void**)&Kp, g_K);
    cudaGetSymbolAddress((void**)&Vp, g_V);
    cudaGetSymbolAddress((void**)&Ap, g_A);

    cudaFuncSetAttribute(gemm_tf32<0,0>, cudaFuncAttributeMaxDynamicSharedMemorySize, (int)GM_SMEM_BYTES);
    cudaFuncSetAttribute(gemm_tf32<0,1>, cudaFuncAttributeMaxDynamicSharedMemorySize, (int)GM_SMEM_BYTES);
    cudaFuncSetAttribute(gemm_tf32<1,0>, cudaFuncAttributeMaxDynamicSharedMemorySize, (int)GM_SMEM_BYTES);

    const dim3 gImg(DIM / 128, S_IMG / 128);
    const dim3 gTxt(DIM / 128, S_TXT / 128);

    // QKV projections (txt tokens rows 0..511, img 512..). V tf32-rounded.
    gemm_tf32<0,0><<<gImg, 256, GM_SMEM_BYTES>>>(hid, wq, bq, Qp, S_TXT);
    gemm_tf32<0,0><<<gImg, 256, GM_SMEM_BYTES>>>(hid, wk, bk, Kp, S_TXT);
    gemm_tf32<0,1><<<gImg, 256, GM_SMEM_BYTES>>>(hid, wv, bv, Vp, S_TXT);
    gemm_tf32<0,0><<<gTxt, 256, GM_SMEM_BYTES>>>(enc, awq, abq, Qp, 0);
    gemm_tf32<0,0><<<gTxt, 256, GM_SMEM_BYTES>>>(enc, awk, abk, Kp, 0);
    gemm_tf32<0,1><<<gTxt, 256, GM_SMEM_BYTES>>>(enc, awv, abv, Vp, 0);

    // rmsnorm + rope; fold 1/sqrt(D) into Q; tf32-round Q and K
    const int nr_blocks = (H * S_TOT) / 8;
    norm_rope<<<nr_blocks, 256>>>(Qp, nq, anq, img_cos, img_sin, txt_cos, txt_sin,
                                  0.08838834764831845f);
    norm_rope<<<nr_blocks, 256>>>(Kp, nk, ank, img_cos, img_sin, txt_cos, txt_sin,
                                  1.0f);

    // joint flash attention (tf32 tensor cores)
    cudaFuncSetAttribute(flash_tf32, cudaFuncAttributeMaxDynamicSharedMemorySize,
                         (int)FL_SMEM_BYTES);
    flash_tf32<<<dim3(S_TOT / 128, H), 256, FL_SMEM_BYTES>>>(Qp, Kp, Vp, Ap);

    // output projections
    gemm_tf32<1,0><<<gImg, 256, GM_SMEM_BYTES>>>(Ap + (size_t)S_TXT * DIM, wo, bo, out, 0);
    gemm_tf32<1,0><<<gTxt, 256, GM_SMEM_BYTES>>>(Ap, awo, abo, out + (size_t)S_IMG * DIM, 0);
}

// round 13
// speedup vs baseline: 5.2706x; 1.2439x over previous
#include <cuda_runtime.h>
#include <math.h>
#include <stdint.h>

#define H      24
#define D      128
#define DIM    3072
#define S_TXT  512
#define S_IMG  2048
#define S_TOT  2560
#define EPS    1e-6f

// ---------------- scratch (device globals; no allocations allowed) ----------
__device__ float g_Q[(size_t)H * S_TOT * D];     // [h][t][d]
__device__ float g_K[(size_t)H * S_TOT * D];
__device__ float g_V[(size_t)H * S_TOT * D];
__device__ float g_A[(size_t)S_TOT * DIM];       // joint attn out (tf32-rounded)
__device__ float g_Wr[(size_t)8 * DIM * DIM];    // tf32-rounded weights, slots 0..7
__device__ float g_hidr[(size_t)S_IMG * DIM];    // tf32-rounded hidden_states
__device__ float g_encr[(size_t)S_TXT * DIM];    // tf32-rounded encoder states

// ---------------- helpers ---------------------------------------------------
__device__ __forceinline__ float tf32r(float x) {
    unsigned u;
    asm("cvt.rna.tf32.f32 %0, %1;" : "=r"(u) : "f"(x));
    return __uint_as_float(u);
}
__device__ __forceinline__ void cp16(uint32_t s, const void* g) {
    asm volatile("cp.async.cg.shared.global [%0], [%1], 16;" :: "r"(s), "l"(g));
}
__device__ __forceinline__ void cp_commit() { asm volatile("cp.async.commit_group;"); }
template <int N>
__device__ __forceinline__ void cp_wait() { asm volatile("cp.async.wait_group %0;" :: "n"(N)); }

// mma.m16n8k8 tf32: A 4 regs (a0:(g,t) a1:(g+8,t) a2:(g,t+4) a3:(g+8,t+4)),
// B 2 regs (b0:(k=t,n=g) b1:(k=t+4,n=g)), C 4 (c0:(g,2t) c1:(g,2t+1) c2/c3: +8 rows)
__device__ __forceinline__ void mma_tf32(float* c, const float* a, float b0, float b1) {
    asm volatile("mma.sync.aligned.m16n8k8.row.col.f32.tf32.tf32.f32 "
                 "{%0,%1,%2,%3}, {%4,%5,%6,%7}, {%8,%9}, {%0,%1,%2,%3};"
        : "+f"(c[0]), "+f"(c[1]), "+f"(c[2]), "+f"(c[3])
        : "r"(__float_as_uint(a[0])), "r"(__float_as_uint(a[1])),
          "r"(__float_as_uint(a[2])), "r"(__float_as_uint(a[3])),
          "r"(__float_as_uint(b0)), "r"(__float_as_uint(b1)));
}

// ---------------------------------------------------------------------------
// Prepass: round fp32 -> tf32 (rna) once, so GEMM mainloops carry no cvt.
// ---------------------------------------------------------------------------
__global__ void __launch_bounds__(256)
conv_w(const float* __restrict__ w0, const float* __restrict__ w1,
       const float* __restrict__ w2, const float* __restrict__ w3,
       const float* __restrict__ w4, const float* __restrict__ w5,
       const float* __restrict__ w6, const float* __restrict__ w7,
       float* __restrict__ dst)
{
    const size_t per = (size_t)DIM * DIM / 4;
    size_t i = (size_t)blockIdx.x * 256 + threadIdx.x;
    if (i >= 8 * per) return;
    const int w = (int)(i / per);
    const size_t j = i - (size_t)w * per;
    const float* src;
    switch (w) {
        case 0: src = w0; break; case 1: src = w1; break;
        case 2: src = w2; break; case 3: src = w3; break;
        case 4: src = w4; break; case 5: src = w5; break;
        case 6: src = w6; break; default: src = w7; break;
    }
    float4 v = ((const float4*)src)[j];
    v.x = tf32r(v.x); v.y = tf32r(v.y); v.z = tf32r(v.z); v.w = tf32r(v.w);
    ((float4*)dst)[i] = v;
}

__global__ void __launch_bounds__(256)
conv_a(const float* __restrict__ src, float* __restrict__ dst, int n4)
{
    int i = blockIdx.x * 256 + threadIdx.x;
    if (i >= n4) return;
    float4 v = ((const float4*)src)[i];
    v.x = tf32r(v.x); v.y = tf32r(v.y); v.z = tf32r(v.z); v.w = tf32r(v.w);
    ((float4*)dst)[i] = v;
}

// ---------------------------------------------------------------------------
// tf32 GEMM core: CTA 128x128, BK=32, 128 threads = 4 warps (2x2),
// warp tile 64x64. Inputs pre-rounded to tf32. Double-buffered cp.async.
// ---------------------------------------------------------------------------
#define GBK  32
#define ASTR 36     // frag bank = 4g + t  (conflict-free)
#define BSTR 136    // frag bank = 8t + g  (conflict-free)
#define GM_SMEM_FLOATS (2*128*ASTR + 2*GBK*BSTR)
#define GM_SMEM_BYTES  (GM_SMEM_FLOATS * sizeof(float))

struct EpiHead { float* C; int head; int row_off; bool rnd; };  // head layout
struct EpiRow  { float* C; };                                   // row-major

template <int MODE>   // 0: head layout, 1: row-major
__device__ __forceinline__ void gemm_core(
    const float* __restrict__ A,     // M x DIM row-major (tf32 values)
    const float* __restrict__ Bw,    // DIM x DIM row-major (tf32 values)
    const float* __restrict__ bias,  // DIM
    int m0, int n0,
    float* Cc, int head, int row_off, bool rnd)
{
    extern __shared__ float gsm[];
    float* As = gsm;                     // [2][128][ASTR]
    float* Bs = gsm + 2 * 128 * ASTR;    // [2][GBK][BSTR]

    const int tid  = threadIdx.x;
    const int warp = tid >> 5, lane = tid & 31;
    const int g = lane >> 2, t = lane & 3;
    const int wm = (warp >> 1) * 64;     // {0, 64}
    const int wn = (warp & 1) * 64;      // {0, 64}

    const uint32_t sA = (uint32_t)__cvta_generic_to_shared(As);
    const uint32_t sB = (uint32_t)__cvta_generic_to_shared(Bs);

    float acc[4][8][4];
    #pragma unroll
    for (int i = 0; i < 4; ++i)
        #pragma unroll
        for (int j = 0; j < 8; ++j)
            #pragma unroll
            for (int r = 0; r < 4; ++r) acc[i][j][r] = 0.f;

    auto prefetch = [&](int kt, int st) {
        const int k0 = kt * GBK;
        #pragma unroll
        for (int i = 0; i < 8; ++i) {
            const int ia = tid + i * 128;                 // 0..1023
            const int ar = ia >> 3, ac = (ia & 7) * 4;    // A: 128 x 32
            cp16(sA + (uint32_t)(st * 128 * ASTR + ar * ASTR + ac) * 4,
                 A + (size_t)(m0 + ar) * DIM + k0 + ac);
            const int br = ia >> 5, bc = (ia & 31) * 4;   // B: 32 x 128
            cp16(sB + (uint32_t)(st * GBK * BSTR + br * BSTR + bc) * 4,
                 Bw + (size_t)(k0 + br) * DIM + n0 + bc);
        }
    };

    prefetch(0, 0);
    cp_commit();

    const int NT = DIM / GBK;   // 96
    for (int kt = 0; kt < NT; ++kt) {
        const int st = kt & 1;
        cp_wait<0>();
        __syncthreads();
        if (kt + 1 < NT) { prefetch(kt + 1, st ^ 1); cp_commit(); }

        const float* Ab = As + st * 128 * ASTR;
        const float* Bb = Bs + st * GBK * BSTR;

        #pragma unroll
        for (int ks = 0; ks < GBK; ks += 8) {
            float a[4][4];
            #pragma unroll
            for (int mt = 0; mt < 4; ++mt) {
                const int row = wm + mt * 16;
                a[mt][0] = Ab[(row + g) * ASTR + ks + t];
                a[mt][1] = Ab[(row + 8 + g) * ASTR + ks + t];
                a[mt][2] = Ab[(row + g) * ASTR + ks + t + 4];
                a[mt][3] = Ab[(row + 8 + g) * ASTR + ks + t + 4];
            }
            float b0[8], b1[8];
            #pragma unroll
            for (int nt = 0; nt < 8; ++nt) {
                const int col = wn + nt * 8 + g;
                b0[nt] = Bb[(ks + t) * BSTR + col];
                b1[nt] = Bb[(ks + t + 4) * BSTR + col];
            }
            #pragma unroll
            for (int mt = 0; mt < 4; ++mt)
                #pragma unroll
                for (int nt = 0; nt < 8; ++nt)
                    mma_tf32(acc[mt][nt], a[mt], b0[nt], b1[nt]);
        }
    }

    // epilogue
    #pragma unroll
    for (int mt = 0; mt < 4; ++mt) {
        const int lr0 = wm + mt * 16 + g;
        const int lr1 = lr0 + 8;
        #pragma unroll
        for (int nt = 0; nt < 8; ++nt) {
            const int cidx = wn + nt * 8 + 2 * t;
            const int n = n0 + cidx;
            float v0 = acc[mt][nt][0] + bias[n];
            float v1 = acc[mt][nt][1] + bias[n + 1];
            float v2 = acc[mt][nt][2] + bias[n];
            float v3 = acc[mt][nt][3] + bias[n + 1];
            if (MODE == 0 && rnd) { v0 = tf32r(v0); v1 = tf32r(v1); v2 = tf32r(v2); v3 = tf32r(v3); }
            if (MODE == 0) {
                float* p0 = Cc + ((size_t)head * S_TOT + row_off + m0 + lr0) * D + cidx;
                float* p1 = Cc + ((size_t)head * S_TOT + row_off + m0 + lr1) * D + cidx;
                *(float2*)p0 = make_float2(v0, v1);
                *(float2*)p1 = make_float2(v2, v3);
            } else {
                *(float2*)(Cc + (size_t)(m0 + lr0) * DIM + n) = make_float2(v0, v1);
                *(float2*)(Cc + (size_t)(m0 + lr1) * DIM + n) = make_float2(v2, v3);
            }
        }
    }
}

// All six QKV projections in one launch. grid (72, 20):
//   bx: qkv = bx/24 (0=Q,1=K,2=V), head = bx%24
//   by: 0..15 -> img rows (A=hidr, slots 0..2, row_off=S_TXT)
//       16..19 -> txt rows (A=encr, slots 3..5, row_off=0)
__global__ void __launch_bounds__(128, 2)
gemm_qkv(const float* __restrict__ hidr, const float* __restrict__ encr,
         const float* __restrict__ Wr,
         const float* __restrict__ bq,  const float* __restrict__ bk,  const float* __restrict__ bv,
         const float* __restrict__ abq, const float* __restrict__ abk, const float* __restrict__ abv,
         float* __restrict__ Q, float* __restrict__ K, float* __restrict__ V)
{
    const int qkv  = blockIdx.x / 24;
    const int head = blockIdx.x % 24;
    const bool istxt = blockIdx.y >= 16;
    const int m0 = (istxt ? blockIdx.y - 16 : blockIdx.y) * 128;
    const float* A = istxt ? encr : hidr;
    const int row_off = istxt ? 0 : S_TXT;
    const int slot = (istxt ? 3 : 0) + qkv;
    const float* Bw = Wr + (size_t)slot * DIM * DIM;
    const float* bias = istxt ? (qkv == 0 ? abq : qkv == 1 ? abk : abv)
                              : (qkv == 0 ? bq  : qkv == 1 ? bk  : bv);
    float* Cc = qkv == 0 ? Q : qkv == 1 ? K : V;
    gemm_core<0>(A, Bw, bias, m0, head * 128, Cc, head, row_off, qkv == 2);
}

// Both output projections in one launch. grid (24, 20):
//   by 0..15 -> img (A = g_A + S_TXT*DIM, slot 6, C = out)
//   by 16..19 -> txt (A = g_A, slot 7, C = out + S_IMG*DIM)
__global__ void __launch_bounds__(128, 2)
gemm_out(const float* __restrict__ Ap, const float* __restrict__ Wr,
         const float* __restrict__ bo, const float* __restrict__ abo,
         float* __restrict__ out)
{
    const bool istxt = blockIdx.y >= 16;
    const int m0 = (istxt ? blockIdx.y - 16 : blockIdx.y) * 128;
    const float* A = istxt ? Ap : Ap + (size_t)S_TXT * DIM;
    const float* Bw = Wr + (size_t)(istxt ? 7 : 6) * DIM * DIM;
    const float* bias = istxt ? abo : bo;
    float* Cc = istxt ? out + (size_t)S_IMG * DIM : out;
    gemm_core<1>(A, Bw, bias, m0, blockIdx.x * 128, Cc, 0, 0, false);
}

// ---------------------------------------------------------------------------
// RMSNorm + RoPE + fold scale + tf32 rounding. One warp per (head, token).
// ---------------------------------------------------------------------------
__global__ void __launch_bounds__(256)
norm_rope(float* __restrict__ X,
          const float* __restrict__ w_img, const float* __restrict__ w_txt,
          const float* __restrict__ img_cos, const float* __restrict__ img_sin,
          const float* __restrict__ txt_cos, const float* __restrict__ txt_sin,
          float scale)
{
    const int warp = (blockIdx.x * blockDim.x + threadIdx.x) >> 5;
    const int lane = threadIdx.x & 31;
    if (warp >= H * S_TOT) return;
    const int t = warp % S_TOT;
    const int h = warp / S_TOT;
    float* row = X + ((size_t)h * S_TOT + t) * D;
    const int d0 = lane * 4;

    float4 x = *(const float4*)(row + d0);
    float ss = x.x * x.x + x.y * x.y + x.z * x.z + x.w * x.w;
    #pragma unroll
    for (int o = 16; o > 0; o >>= 1) ss += __shfl_xor_sync(0xffffffffu, ss, o);
    const float inv = rsqrtf(ss * (1.f / 128.f) + EPS);

    const float* w; const float* cs; const float* sn;
    if (t < S_TXT) { w = w_txt; cs = txt_cos + (size_t)t * D;           sn = txt_sin + (size_t)t * D; }
    else           { w = w_img; cs = img_cos + (size_t)(t - S_TXT) * D; sn = img_sin + (size_t)(t - S_TXT) * D; }

    float4 wv = *(const float4*)(w + d0);
    float4 c  = *(const float4*)(cs + d0);
    float4 s  = *(const float4*)(sn + d0);

    const float y0 = x.x * inv * wv.x;
    const float y1 = x.y * inv * wv.y;
    const float y2 = x.z * inv * wv.z;
    const float y3 = x.w * inv * wv.w;

    float4 o;
    o.x = tf32r((y0 * c.x - y1 * s.x) * scale);
    o.y = tf32r((y1 * c.y + y0 * s.y) * scale);
    o.z = tf32r((y2 * c.z - y3 * s.z) * scale);
    o.w = tf32r((y3 * c.w + y2 * s.w) * scale);
    *(float4*)(row + d0) = o;
}

// ---------------------------------------------------------------------------
// tf32 tensor-core flash attention (R11 design; epilogue now tf32-rounds g_A).
// grid (S_TOT/128, H), 256 threads (8 warps). BM=128, BN=64, D=128.
// ---------------------------------------------------------------------------
#define KSTR 132
#define VSTR 136
#define PSTR 68
#define FL_NT (S_TOT / 64)
#define FL_SMEM_FLOATS (2*64*KSTR + 2*64*VSTR + 128*PSTR)
#define FL_SMEM_BYTES  (FL_SMEM_FLOATS * sizeof(float))

__global__ void __launch_bounds__(256)
flash_tf32(const float* __restrict__ Q, const float* __restrict__ K,
           const float* __restrict__ V, float* __restrict__ Aout)
{
    extern __shared__ float fsm[];
    float* Ks = fsm;                    // [2][64][KSTR]
    float* Vs = Ks + 2 * 64 * KSTR;     // [2][64][VSTR]
    float* Ps = Vs + 2 * 64 * VSTR;     // [128][PSTR]

    const int tid  = threadIdx.x;
    const int warp = tid >> 5, lane = tid & 31;
    const int g = lane >> 2, t = lane & 3;
    const int h  = blockIdx.y;
    const int m0 = blockIdx.x * 128;
    const int wr = warp * 16;

    const uint32_t sK = (uint32_t)__cvta_generic_to_shared(Ks);
    const uint32_t sV = (uint32_t)__cvta_generic_to_shared(Vs);

    const float* Qg = Q + ((size_t)h * S_TOT + m0 + wr) * D;
    const float* Kg = K + (size_t)h * S_TOT * D;
    const float* Vg = V + (size_t)h * S_TOT * D;

    float q[16][4];
    #pragma unroll
    for (int kb = 0; kb < 16; ++kb) {
        q[kb][0] = Qg[(size_t)g * D + kb * 8 + t];
        q[kb][1] = Qg[(size_t)(g + 8) * D + kb * 8 + t];
        q[kb][2] = Qg[(size_t)g * D + kb * 8 + t + 4];
        q[kb][3] = Qg[(size_t)(g + 8) * D + kb * 8 + t + 4];
    }

    float ofr[16][4];
    #pragma unroll
    for (int i = 0; i < 16; ++i)
        #pragma unroll
        for (int j = 0; j < 4; ++j) ofr[i][j] = 0.f;

    float m0r = -1e30f, m1r = -1e30f, l0 = 0.f, l1 = 0.f;

    auto prefetch = [&](int kt, int st) {
        const float* kg = Kg + (size_t)kt * 64 * D;
        const float* vg = Vg + (size_t)kt * 64 * D;
        #pragma unroll
        for (int i = 0; i < 8; ++i) {
            const int idx = tid + i * 256;
            const int r = idx >> 5, c = (idx & 31) << 2;
            cp16(sK + (uint32_t)(st * 64 * KSTR + r * KSTR + c) * 4, kg + (size_t)r * D + c);
            cp16(sV + (uint32_t)(st * 64 * VSTR + r * VSTR + c) * 4, vg + (size_t)r * D + c);
        }
    };

    prefetch(0, 0);
    cp_commit();

    for (int kt = 0; kt < FL_NT; ++kt) {
        const int st = kt & 1;
        if (kt + 1 < FL_NT) { prefetch(kt + 1, st ^ 1); cp_commit(); cp_wait<1>(); }
        else                { cp_wait<0>(); }
        __syncthreads();

        const float* Kb = Ks + st * 64 * KSTR;
        const float* Vb = Vs + st * 64 * VSTR;

        float sfr[8][4];
        #pragma unroll
        for (int i = 0; i < 8; ++i)
            #pragma unroll
            for (int j = 0; j < 4; ++j) sfr[i][j] = 0.f;

        #pragma unroll
        for (int kb = 0; kb < 16; ++kb) {
            #pragma unroll
            for (int nt = 0; nt < 8; ++nt) {
                const float b0 = Kb[(nt * 8 + g) * KSTR + kb * 8 + t];
                const float b1 = Kb[(nt * 8 + g) * KSTR + kb * 8 + t + 4];
                mma_tf32(sfr[nt], q[kb], b0, b1);
            }
        }

        float mx0 = -1e30f, mx1 = -1e30f;
        #pragma unroll
        for (int nt = 0; nt < 8; ++nt) {
            mx0 = fmaxf(mx0, fmaxf(sfr[nt][0], sfr[nt][1]));
            mx1 = fmaxf(mx1, fmaxf(sfr[nt][2], sfr[nt][3]));
        }
        mx0 = fmaxf(mx0, __shfl_xor_sync(0xffffffffu, mx0, 1));
        mx0 = fmaxf(mx0, __shfl_xor_sync(0xffffffffu, mx0, 2));
        mx1 = fmaxf(mx1, __shfl_xor_sync(0xffffffffu, mx1, 1));
        mx1 = fmaxf(mx1, __shfl_xor_sync(0xffffffffu, mx1, 2));

        const float mn0 = fmaxf(m0r, mx0);
        const float mn1 = fmaxf(m1r, mx1);
        const float al0 = __expf(m0r - mn0);
        const float al1 = __expf(m1r - mn1);
        m0r = mn0; m1r = mn1;

        float* prow0 = Ps + (wr + g) * PSTR;
        float* prow1 = Ps + (wr + 8 + g) * PSTR;
        float s0 = 0.f, s1 = 0.f;
        #pragma unroll
        for (int nt = 0; nt < 8; ++nt) {
            const float p00 = tf32r(__expf(sfr[nt][0] - mn0));
            const float p01 = tf32r(__expf(sfr[nt][1] - mn0));
            const float p10 = tf32r(__expf(sfr[nt][2] - mn1));
            const float p11 = tf32r(__expf(sfr[nt][3] - mn1));
            s0 += p00 + p01;
            s1 += p10 + p11;
            *(float2*)(prow0 + nt * 8 + 2 * t) = make_float2(p00, p01);
            *(float2*)(prow1 + nt * 8 + 2 * t) = make_float2(p10, p11);
        }
        l0 = l0 * al0 + s0;
        l1 = l1 * al1 + s1;

        #pragma unroll
        for (int nt = 0; nt < 16; ++nt) {
            ofr[nt][0] *= al0; ofr[nt][1] *= al0;
            ofr[nt][2] *= al1; ofr[nt][3] *= al1;
        }
        __syncwarp();

        #pragma unroll
        for (int kb = 0; kb < 8; ++kb) {
            float a[4];
            a[0] = Ps[(wr + g) * PSTR + kb * 8 + t];
            a[1] = Ps[(wr + 8 + g) * PSTR + kb * 8 + t];
            a[2] = Ps[(wr + g) * PSTR + kb * 8 + t + 4];
            a[3] = Ps[(wr + 8 + g) * PSTR + kb * 8 + t + 4];
            #pragma unroll
            for (int nt = 0; nt < 16; ++nt) {
                const float b0 = Vb[(kb * 8 + t) * VSTR + nt * 8 + g];
                const float b1 = Vb[(kb * 8 + t + 4) * VSTR + nt * 8 + g];
                mma_tf32(ofr[nt], a, b0, b1);
            }
        }
        __syncthreads();
    }

    l0 += __shfl_xor_sync(0xffffffffu, l0, 1);
    l0 += __shfl_xor_sync(0xffffffffu, l0, 2);
    l1 += __shfl_xor_sync(0xffffffffu, l1, 1);
    l1 += __shfl_xor_sync(0xffffffffu, l1, 2);
    const float i0 = 1.f / l0;
    const float i1 = 1.f / l1;

    const int tok0 = m0 + wr + g;
    const int tok1 = tok0 + 8;
    #pragma unroll
    for (int nt = 0; nt < 16; ++nt) {
        *(float2*)(Aout + (size_t)tok0 * DIM + h * D + nt * 8 + 2 * t) =
            make_float2(tf32r(ofr[nt][0] * i0), tf32r(ofr[nt][1] * i0));
        *(float2*)(Aout + (size_t)tok1 * DIM + h * D + nt * 8 + 2 * t) =
            make_float2(tf32r(ofr[nt][2] * i1), tf32r(ofr[nt][3] * i1));
    }
}

// ---------------------------------------------------------------------------
extern "C" void kernel_launch(void* const* d_in, const int* in_sizes, int n_in,
                              void* d_out, int out_size)
{
    const float* hid     = (const float*)d_in[0];
    const float* enc     = (const float*)d_in[1];
    const float* img_cos = (const float*)d_in[2];
    const float* img_sin = (const float*)d_in[3];
    const float* txt_cos = (const float*)d_in[4];
    const float* txt_sin = (const float*)d_in[5];
    const float* wq  = (const float*)d_in[6];
    const float* bq  = (const float*)d_in[7];
    const float* wk  = (const float*)d_in[8];
    const float* bk  = (const float*)d_in[9];
    const float* wv  = (const float*)d_in[10];
    const float* bv  = (const float*)d_in[11];
    const float* awq = (const float*)d_in[12];
    const float* abq = (const float*)d_in[13];
    const float* awk = (const float*)d_in[14];
    const float* abk = (const float*)d_in[15];
    const float* awv = (const float*)d_in[16];
    const float* abv = (const float*)d_in[17];
    const float* wo  = (const float*)d_in[18];
    const float* bo  = (const float*)d_in[19];
    const float* awo = (const float*)d_in[20];
    const float* abo = (const float*)d_in[21];
    const float* nq  = (const float*)d_in[22];
    const float* nk  = (const float*)d_in[23];
    const float* anq = (const float*)d_in[24];
    const float* ank = (const float*)d_in[25];
    float* out = (float*)d_out;

    float *Qp, *Kp, *Vp, *Ap, *Wr, *hidr, *encr;
    cudaGetSymbolAddress((void**)&Qp, g_Q);
    cudaGetSymbolAddress((void**)&Kp, g_K);
    cudaGetSymbolAddress((void**)&Vp, g_V);
    cudaGetSymbolAddress((void**)&Ap, g_A);
    cudaGetSymbolAddress((void**)&Wr, g_Wr);
    cudaGetSymbolAddress((void**)&hidr, g_hidr);
    cudaGetSymbolAddress((void**)&encr, g_encr);

    cudaFuncSetAttribute(gemm_qkv, cudaFuncAttributeMaxDynamicSharedMemorySize, (int)GM_SMEM_BYTES);
    cudaFuncSetAttribute(gemm_out, cudaFuncAttributeMaxDynamicSharedMemorySize, (int)GM_SMEM_BYTES);
    cudaFuncSetAttribute(flash_tf32, cudaFuncAttributeMaxDynamicSharedMemorySize, (int)FL_SMEM_BYTES);

    // prepass: tf32-round weights (slots: 0 wq 1 wk 2 wv | 3 awq 4 awk 5 awv | 6 wo 7 awo)
    {
        const size_t tot4 = (size_t)8 * DIM * DIM / 4;
        conv_w<<<(unsigned)((tot4 + 255) / 256), 256>>>(wq, wk, wv, awq, awk, awv, wo, awo, Wr);
        conv_a<<<(S_IMG * DIM / 4 + 255) / 256, 256>>>(hid, hidr, S_IMG * DIM / 4);
        conv_a<<<(S_TXT * DIM / 4 + 255) / 256, 256>>>(enc, encr, S_TXT * DIM / 4);
    }

    // all six QKV projections in one launch
    gemm_qkv<<<dim3(72, 20), 128, GM_SMEM_BYTES>>>(hidr, encr, Wr,
                                                   bq, bk, bv, abq, abk, abv,
                                                   Qp, Kp, Vp);

    // rmsnorm + rope; fold 1/sqrt(D) into Q; tf32-round Q and K
    const int nr_blocks = (H * S_TOT) / 8;
    norm_rope<<<nr_blocks, 256>>>(Qp, nq, anq, img_cos, img_sin, txt_cos, txt_sin,
                                  0.08838834764831845f);
    norm_rope<<<nr_blocks, 256>>>(Kp, nk, ank, img_cos, img_sin, txt_cos, txt_sin,
                                  1.0f);

    // joint flash attention (tf32 tensor cores)
    flash_tf32<<<dim3(S_TOT / 128, H), 256, FL_SMEM_BYTES>>>(Qp, Kp, Vp, Ap);

    // both output projections in one launch
    gemm_out<<<dim3(24, 20), 128, GM_SMEM_BYTES>>>(Ap, Wr, bo, abo, out);
}